// round 3
// baseline (speedup 1.0000x reference)
#include <cuda_runtime.h>
#include <math.h>

#define BB 2
#define NN 2048
#define DM 1024
#define HH 16
#define DH 64
#define MM (BB*NN)      /* 4096 */
#define BH (BB*HH)      /* 32   */
#define EPSF 1e-6f
#define PAD 68

// Scratch (device globals; no allocation allowed)
__device__ float g_Q [BH*NN*DH];   // [bh][n][d]
__device__ float g_Kt[BH*DH*NN];   // [bh][d][n]  (transposed for attention)
__device__ float g_V [BH*NN*DH];   // [bh][n][d]
__device__ float g_O [BH*NN*DH];   // [bh][n][d]  (attention output, pre-Wo)

// ---------------------------------------------------------------------------
// Projection GEMM: Y = X @ W   (X [4096][1024], W [1024][1024])
// mode 0 -> g_Q heads layout, 1 -> g_Kt transposed, 2 -> g_V heads layout
// col tile (64) == one head exactly.
// ---------------------------------------------------------------------------
__global__ __launch_bounds__(256) void gemm_proj(
    const float* __restrict__ X, const float* __restrict__ W, int mode)
{
    __shared__ float As[16][PAD];   // [k][m]
    __shared__ float Bs[16][PAD];   // [k][n]
    const int tid = threadIdx.x;
    const int tx = tid & 15, ty = tid >> 4;
    const int m0 = blockIdx.y * 64;
    const int h  = blockIdx.x;
    const int c0 = h * 64;
    const int arow = tid >> 2, akq = tid & 3;
    const int bkk = tid >> 4, bc4 = tid & 15;
    float acc[4][4] = {};

    for (int k0 = 0; k0 < DM; k0 += 16) {
        float4 a = *(const float4*)&X[(size_t)(m0 + arow)*DM + k0 + akq*4];
        float4 b = *(const float4*)&W[(size_t)(k0 + bkk)*DM + c0 + bc4*4];
        __syncthreads();
        As[akq*4+0][arow] = a.x;
        As[akq*4+1][arow] = a.y;
        As[akq*4+2][arow] = a.z;
        As[akq*4+3][arow] = a.w;
        *(float4*)&Bs[bkk][bc4*4] = b;
        __syncthreads();
        #pragma unroll
        for (int kk = 0; kk < 16; kk++) {
            float4 av = *(const float4*)&As[kk][ty*4];
            float4 bv = *(const float4*)&Bs[kk][tx*4];
            acc[0][0] += av.x*bv.x; acc[0][1] += av.x*bv.y; acc[0][2] += av.x*bv.z; acc[0][3] += av.x*bv.w;
            acc[1][0] += av.y*bv.x; acc[1][1] += av.y*bv.y; acc[1][2] += av.y*bv.z; acc[1][3] += av.y*bv.w;
            acc[2][0] += av.z*bv.x; acc[2][1] += av.z*bv.y; acc[2][2] += av.z*bv.z; acc[2][3] += av.z*bv.w;
            acc[3][0] += av.w*bv.x; acc[3][1] += av.w*bv.y; acc[3][2] += av.w*bv.z; acc[3][3] += av.w*bv.w;
        }
    }

    float* dst = (mode == 0) ? g_Q : (mode == 1) ? g_Kt : g_V;
    #pragma unroll
    for (int i = 0; i < 4; i++) {
        int m = m0 + ty*4 + i;
        int b = m >> 11;            // / NN
        int n = m & (NN-1);
        if (mode == 1) {
            #pragma unroll
            for (int j = 0; j < 4; j++) {
                int d = tx*4 + j;
                dst[((size_t)(b*HH + h)*DH + d)*NN + n] = acc[i][j];
            }
        } else {
            float4 o = make_float4(acc[i][0], acc[i][1], acc[i][2], acc[i][3]);
            *(float4*)&dst[((size_t)(b*HH + h)*NN + n)*DH + tx*4] = o;
        }
    }
}

// ---------------------------------------------------------------------------
// L2-normalize Q rows ([bh][n][d], warp per row of 64)
// ---------------------------------------------------------------------------
__global__ __launch_bounds__(256) void norm_q_rows()
{
    int w    = (blockIdx.x * 256 + threadIdx.x) >> 5;   // 0 .. BH*NN-1
    int lane = threadIdx.x & 31;
    float* p = g_Q + (size_t)w * DH;
    float a = p[lane], b = p[lane + 32];
    float ss = a*a + b*b;
    #pragma unroll
    for (int off = 16; off; off >>= 1) ss += __shfl_xor_sync(0xffffffffu, ss, off);
    float sc = 1.0f / (sqrtf(ss) + EPSF);
    p[lane]      = a * sc;
    p[lane + 32] = b * sc;
}

// ---------------------------------------------------------------------------
// L2-normalize K columns ([bh][d][n], thread per n; coalesced across threads)
// ---------------------------------------------------------------------------
__global__ __launch_bounds__(256) void norm_k_cols()
{
    int gc = blockIdx.x * 256 + threadIdx.x;            // 0 .. BH*NN-1
    int bh = gc >> 11, n = gc & (NN-1);
    float* p = g_Kt + (size_t)bh * DH * NN + n;
    float v[DH];
    float ss = 0.f;
    #pragma unroll
    for (int d = 0; d < DH; d++) { v[d] = p[(size_t)d*NN]; ss += v[d]*v[d]; }
    float sc = 1.0f / (sqrtf(ss) + EPSF);
    #pragma unroll
    for (int d = 0; d < DH; d++) p[(size_t)d*NN] = v[d]*sc;
}

// ---------------------------------------------------------------------------
// Flash-style causal attention. Block = 64 queries of one (b,h).
// Thread (lq = tid/4, g = tid&3). Score/P ownership: j = 16u + 4g + v.
// Output dim ownership:                         d = 16u + 4g + v.
// ---------------------------------------------------------------------------
__global__ __launch_bounds__(256) void attn_kernel()
{
    __shared__ float Qs[64*PAD];   // [q][d]
    __shared__ float KV[64*PAD];   // K stage: [d][j]; V stage: [j][d]
    const int tid  = threadIdx.x;
    const int qt   = blockIdx.x;
    const int bh   = blockIdx.y;
    const int qbase = qt * 64;
    const int lq   = tid >> 2;
    const int g    = tid & 3;
    const int lane = tid & 31;

    const float* Qp = g_Q  + (size_t)bh * NN * DH;
    const float* Kp = g_Kt + (size_t)bh * DH * NN;
    const float* Vp = g_V  + (size_t)bh * NN * DH;

    #pragma unroll
    for (int r = 0; r < 4; r++) {
        int idx = tid + 256*r;
        int q = idx >> 4, c4 = idx & 15;
        *(float4*)&Qs[q*PAD + c4*4] = *(const float4*)&Qp[(size_t)(qbase + q)*DH + c4*4];
    }

    float mrun = -INFINITY, lrun = 0.f;
    float acc[4][4] = {};

    for (int kt = 0; kt <= qt; kt++) {
        const int kbase = kt * 64;
        __syncthreads();                       // prior-iter KV reads (and Qs load) done
        #pragma unroll
        for (int r = 0; r < 4; r++) {          // K tile, transposed layout [d][j]
            int idx = tid + 256*r;
            int d = idx >> 4, c4 = idx & 15;
            *(float4*)&KV[d*PAD + c4*4] = *(const float4*)&Kp[(size_t)d*NN + kbase + c4*4];
        }
        __syncthreads();

        // ---- scores: s[u][v] = q . k_j, j = 16u+4g+v ----
        float s[4][4];
        #pragma unroll
        for (int u = 0; u < 4; u++) { s[u][0]=0.f; s[u][1]=0.f; s[u][2]=0.f; s[u][3]=0.f; }
        #pragma unroll 4
        for (int d = 0; d < 64; d++) {
            float qa = Qs[lq*PAD + d];
            #pragma unroll
            for (int u = 0; u < 4; u++) {
                float4 kv = *(const float4*)&KV[d*PAD + 16*u + 4*g];
                s[u][0] += qa*kv.x; s[u][1] += qa*kv.y; s[u][2] += qa*kv.z; s[u][3] += qa*kv.w;
            }
        }
        __syncthreads();                       // K reads done
        #pragma unroll
        for (int r = 0; r < 4; r++) {          // V tile [j][d]
            int idx = tid + 256*r;
            int j = idx >> 4, c4 = idx & 15;
            *(float4*)&KV[j*PAD + c4*4] = *(const float4*)&Vp[(size_t)(kbase + j)*DH + c4*4];
        }

        // ---- online softmax (registers + quad shuffles) ----
        const bool diag = (kt == qt);
        float tmax = -INFINITY;
        #pragma unroll
        for (int u = 0; u < 4; u++)
            #pragma unroll
            for (int v = 0; v < 4; v++) {
                float sv = s[u][v] * 0.125f;   // 1/sqrt(64)
                int j = 16*u + 4*g + v;
                if (diag && j > lq) sv = -INFINITY;
                s[u][v] = sv;
                tmax = fmaxf(tmax, sv);
            }
        tmax = fmaxf(tmax, __shfl_xor_sync(0xffffffffu, tmax, 1));
        tmax = fmaxf(tmax, __shfl_xor_sync(0xffffffffu, tmax, 2));
        float mnew = fmaxf(mrun, tmax);
        float corr = __expf(mrun - mnew);
        float tsum = 0.f;
        #pragma unroll
        for (int u = 0; u < 4; u++)
            #pragma unroll
            for (int v = 0; v < 4; v++) {
                float pp = __expf(s[u][v] - mnew);
                s[u][v] = pp;
                tsum += pp;
            }
        tsum += __shfl_xor_sync(0xffffffffu, tsum, 1);
        tsum += __shfl_xor_sync(0xffffffffu, tsum, 2);
        lrun = lrun*corr + tsum;
        mrun = mnew;
        #pragma unroll
        for (int u = 0; u < 4; u++) { acc[u][0]*=corr; acc[u][1]*=corr; acc[u][2]*=corr; acc[u][3]*=corr; }

        __syncthreads();                       // V tile ready

        // ---- AV: broadcast p across quad via shuffle ----
        #pragma unroll
        for (int u = 0; u < 4; u++)
            #pragma unroll
            for (int gg = 0; gg < 4; gg++)
                #pragma unroll
                for (int v = 0; v < 4; v++) {
                    int j = 16*u + 4*gg + v;
                    float p = __shfl_sync(0xffffffffu, s[u][v], (lane & ~3) | gg);
                    #pragma unroll
                    for (int uu = 0; uu < 4; uu++) {
                        float4 v4 = *(const float4*)&KV[j*PAD + 16*uu + 4*g];
                        acc[uu][0] += p*v4.x; acc[uu][1] += p*v4.y;
                        acc[uu][2] += p*v4.z; acc[uu][3] += p*v4.w;
                    }
                }
    }

    float inv = 1.0f / lrun;
    float* Op = g_O + (size_t)bh * NN * DH + (size_t)(qbase + lq) * DH;
    #pragma unroll
    for (int u = 0; u < 4; u++) {
        float4 o = make_float4(acc[u][0]*inv, acc[u][1]*inv, acc[u][2]*inv, acc[u][3]*inv);
        *(float4*)&Op[16*u + 4*g] = o;
    }
}

// ---------------------------------------------------------------------------
// Output GEMM: out = V_hat @ Wo + bo, V_hat gathered from g_O heads layout.
// ---------------------------------------------------------------------------
__global__ __launch_bounds__(256) void gemm_out(
    const float* __restrict__ Wo, const float* __restrict__ bo, float* __restrict__ out)
{
    __shared__ float As[16][PAD];
    __shared__ float Bs[16][PAD];
    const int tid = threadIdx.x;
    const int tx = tid & 15, ty = tid >> 4;
    const int m0 = blockIdx.y * 64;
    const int c0 = blockIdx.x * 64;
    const int arow = tid >> 2, akq = tid & 3;
    const int bkk = tid >> 4, bc4 = tid & 15;
    const int am = m0 + arow;
    const int ab = am >> 11, an = am & (NN-1);
    float acc[4][4] = {};

    for (int k0 = 0; k0 < DM; k0 += 16) {
        int k = k0 + akq*4;
        int h = k >> 6, d = k & 63;
        float4 a = *(const float4*)&g_O[(((size_t)ab*HH + h)*NN + an)*DH + d];
        float4 b = *(const float4*)&Wo[(size_t)(k0 + bkk)*DM + c0 + bc4*4];
        __syncthreads();
        As[akq*4+0][arow] = a.x;
        As[akq*4+1][arow] = a.y;
        As[akq*4+2][arow] = a.z;
        As[akq*4+3][arow] = a.w;
        *(float4*)&Bs[bkk][bc4*4] = b;
        __syncthreads();
        #pragma unroll
        for (int kk = 0; kk < 16; kk++) {
            float4 av = *(const float4*)&As[kk][ty*4];
            float4 bv = *(const float4*)&Bs[kk][tx*4];
            acc[0][0] += av.x*bv.x; acc[0][1] += av.x*bv.y; acc[0][2] += av.x*bv.z; acc[0][3] += av.x*bv.w;
            acc[1][0] += av.y*bv.x; acc[1][1] += av.y*bv.y; acc[1][2] += av.y*bv.z; acc[1][3] += av.y*bv.w;
            acc[2][0] += av.z*bv.x; acc[2][1] += av.z*bv.y; acc[2][2] += av.z*bv.z; acc[2][3] += av.z*bv.w;
            acc[3][0] += av.w*bv.x; acc[3][1] += av.w*bv.y; acc[3][2] += av.w*bv.z; acc[3][3] += av.w*bv.w;
        }
    }

    float4 bv = *(const float4*)&bo[c0 + tx*4];
    #pragma unroll
    for (int i = 0; i < 4; i++) {
        int m = m0 + ty*4 + i;
        float4 o = make_float4(acc[i][0] + bv.x, acc[i][1] + bv.y,
                               acc[i][2] + bv.z, acc[i][3] + bv.w);
        *(float4*)&out[(size_t)m*DM + c0 + tx*4] = o;
    }
}

// ---------------------------------------------------------------------------
extern "C" void kernel_launch(void* const* d_in, const int* in_sizes, int n_in,
                              void* d_out, int out_size)
{
    const float* X  = (const float*)d_in[0];
    const float* Wq = (const float*)d_in[1];
    const float* Wk = (const float*)d_in[2];
    const float* Wv = (const float*)d_in[3];
    const float* Wo = (const float*)d_in[4];
    const float* bo = (const float*)d_in[5];
    float* out = (float*)d_out;

    dim3 gg(16, 64);                 // (col tiles, row tiles)
    gemm_proj<<<gg, 256>>>(X, Wq, 0);
    gemm_proj<<<gg, 256>>>(X, Wk, 1);
    gemm_proj<<<gg, 256>>>(X, Wv, 2);
    norm_q_rows<<<(BH*NN)/8, 256>>>();        // 8192 blocks, warp per row
    norm_k_cols<<<(BH*NN)/256, 256>>>();      // 256 blocks, thread per column
    attn_kernel<<<dim3(NN/64, BH), 256>>>();  // (32, 32)
    gemm_out<<<gg, 256>>>(Wo, bo, out);
}

// round 7
// speedup vs baseline: 2.0088x; 2.0088x over previous
#include <cuda_runtime.h>
#include <cstdint>
#include <math.h>

#define BB 2
#define NN 2048
#define DM 1024
#define HH 16
#define DH 64
#define MM (BB*NN)      /* 4096 */
#define BH (BB*HH)      /* 32   */
#define EPSF 1e-6f
#define PAD 68

// ---------------- device scratch (no allocation allowed) -------------------
__device__ float g_Q [BH*NN*DH];     // [bh][n][d]  normalized Q
__device__ float g_Kt[BH*DH*NN];     // [bh][d][n]  normalized K, transposed
__device__ float g_V [BH*NN*DH];     // [bh][n][d]
__device__ float g_O [BH*NN*DH];     // [bh][n][d]  attention out (tf32-rounded)
__device__ float g_Wt[4*DM*DM];      // W^T for Wq,Wk,Wv,Wo (tf32-rounded)
__device__ float g_Xr[MM*DM];        // X rounded to tf32

// ---------------- helpers ---------------------------------------------------
__device__ __forceinline__ float tf32r(float x) {
    float y; asm("cvt.rna.tf32.f32 %0, %1;" : "=f"(y) : "f"(x)); return y;
}
__device__ __forceinline__ void cp16(uint32_t dst, const void* src) {
    asm volatile("cp.async.cg.shared.global [%0], [%1], 16;" :: "r"(dst), "l"(src));
}
__device__ __forceinline__ void cp_commit() { asm volatile("cp.async.commit_group;"); }
template<int N> __device__ __forceinline__ void cp_wait() {
    asm volatile("cp.async.wait_group %0;" :: "n"(N));
}
__device__ __forceinline__ uint32_t smem_u32(const void* p) {
    uint32_t a;
    asm("{ .reg .u64 t; cvta.to.shared.u64 t, %1; cvt.u32.u64 %0, t; }" : "=r"(a) : "l"(p));
    return a;
}
__device__ __forceinline__ void mma_tf32(float* c, const uint32_t* a, const uint32_t* b) {
    asm volatile(
        "mma.sync.aligned.m16n8k8.row.col.f32.tf32.tf32.f32 "
        "{%0,%1,%2,%3}, {%4,%5,%6,%7}, {%8,%9}, {%0,%1,%2,%3};"
        : "+f"(c[0]), "+f"(c[1]), "+f"(c[2]), "+f"(c[3])
        : "r"(a[0]), "r"(a[1]), "r"(a[2]), "r"(a[3]), "r"(b[0]), "r"(b[1]));
}

// ---------------------------------------------------------------------------
// Pre-passes: round X to tf32; transpose + round weights
// ---------------------------------------------------------------------------
__global__ __launch_bounds__(256) void round_x(const float* __restrict__ X)
{
    int i = blockIdx.x * 256 + threadIdx.x;
    float4 v = ((const float4*)X)[i];
    v.x = tf32r(v.x); v.y = tf32r(v.y); v.z = tf32r(v.z); v.w = tf32r(v.w);
    ((float4*)g_Xr)[i] = v;
}

__global__ __launch_bounds__(256) void transpose_w(const float* __restrict__ W, int slot)
{
    __shared__ float ts[32][33];
    float* Wt = g_Wt + (size_t)slot * DM * DM;
    int bx = blockIdx.x * 32, by = blockIdx.y * 32;
    #pragma unroll
    for (int i = 0; i < 32; i += 8)
        ts[threadIdx.y + i][threadIdx.x] = W[(size_t)(by + threadIdx.y + i) * DM + bx + threadIdx.x];
    __syncthreads();
    #pragma unroll
    for (int i = 0; i < 32; i += 8)
        Wt[(size_t)(bx + threadIdx.y + i) * DM + by + threadIdx.x] = tf32r(ts[threadIdx.x][threadIdx.y + i]);
}

// ---------------------------------------------------------------------------
// mma.sync tf32 GEMM: C[4096 x 1024] = A @ Bt^T   (Bt is [n][k])
// BM=128 BN=128 BK=32, 256 threads = 8 warps (2 x 4), warp tile 64 x 32.
// mode 0: Q heads layout   1: Kt transposed   2: V heads layout
// mode 3: out = D + bo (A gathered from g_O heads layout)
// ---------------------------------------------------------------------------
#define BK 32
#define LDS_ROW 36                       /* floats per smem row (pad) */
#define TILE_F (128*LDS_ROW)             /* floats per tile buffer */
#define GEMM_SMEM (4*TILE_F*4)           /* 2 bufs x (A+B) x 4 B = 73728 */
#define KTILES (DM/BK)

__global__ __launch_bounds__(256, 1) void gemm_tc(
    const float* __restrict__ A, const float* __restrict__ Bt,
    const float* __restrict__ bias, float* __restrict__ out, int mode)
{
    extern __shared__ float sm[];
    float* sA[2] = { sm,            sm + 2*TILE_F };
    float* sB[2] = { sm + TILE_F,   sm + 3*TILE_F };

    const int tid  = threadIdx.x;
    const int wid  = tid >> 5;
    const int lane = tid & 31;
    const int lr   = lane >> 2;          // 0..7
    const int lc   = lane & 3;           // 0..3
    const int wm   = (wid & 1) * 64;     // warp m offset in tile
    const int wn   = (wid >> 1) * 32;    // warp n offset in tile
    const int m0   = blockIdx.y * 128;
    const int c0   = blockIdx.x * 128;

    // per-thread load coords: row = tid>>1 (0..127), half = tid&1
    const int lrow = tid >> 1, lhalf = tid & 1;
    const int am = m0 + lrow;
    const int ab = am >> 11, an = am & (NN - 1);
    const float* brow_base = Bt + (size_t)(c0 + lrow) * DM;
    const uint32_t sa_u[2] = { smem_u32(sA[0]), smem_u32(sA[1]) };
    const uint32_t sb_u[2] = { smem_u32(sB[0]), smem_u32(sB[1]) };
    const uint32_t dst_off = (uint32_t)lrow * (LDS_ROW*4) + (uint32_t)lhalf * 64;

    auto load_tile = [&](int t, int buf) {
        const int k0 = t * BK + lhalf * 16;
        const float* arow;
        if (mode == 3) {
            arow = g_O + ((size_t)(ab * HH + (k0 >> 6)) * NN + an) * DH + (k0 & 63);
        } else {
            arow = A + (size_t)am * DM + k0;
        }
        const float* brow = brow_base + k0;
        #pragma unroll
        for (int f = 0; f < 4; f++) {
            cp16(sa_u[buf] + dst_off + f * 16, arow + f * 4);
            cp16(sb_u[buf] + dst_off + f * 16, brow + f * 4);
        }
    };

    float acc[4][4][4] = {};             // [mt][nt][frag]

    load_tile(0, 0);
    cp_commit();

    for (int t = 0; t < KTILES; t++) {
        const int p = t & 1;
        if (t + 1 < KTILES) {
            load_tile(t + 1, 1 - p);
            cp_commit();
            cp_wait<1>();
        } else {
            cp_wait<0>();
        }
        __syncthreads();

        const float* Ab = sA[p];
        const float* Bb = sB[p];
        #pragma unroll
        for (int kk = 0; kk < 4; kk++) {
            const int k0 = kk * 8;
            uint32_t af[4][4], bf[4][2];
            #pragma unroll
            for (int mt = 0; mt < 4; mt++) {
                const int rb = wm + mt * 16;
                af[mt][0] = __float_as_uint(Ab[(rb +     lr) * LDS_ROW + k0 +     lc]);
                af[mt][1] = __float_as_uint(Ab[(rb + 8 + lr) * LDS_ROW + k0 +     lc]);
                af[mt][2] = __float_as_uint(Ab[(rb +     lr) * LDS_ROW + k0 + 4 + lc]);
                af[mt][3] = __float_as_uint(Ab[(rb + 8 + lr) * LDS_ROW + k0 + 4 + lc]);
            }
            #pragma unroll
            for (int nt = 0; nt < 4; nt++) {
                const int cb = wn + nt * 8;
                bf[nt][0] = __float_as_uint(Bb[(cb + lr) * LDS_ROW + k0 +     lc]);
                bf[nt][1] = __float_as_uint(Bb[(cb + lr) * LDS_ROW + k0 + 4 + lc]);
            }
            #pragma unroll
            for (int mt = 0; mt < 4; mt++)
                #pragma unroll
                for (int nt = 0; nt < 4; nt++)
                    mma_tf32(acc[mt][nt], af[mt], bf[nt]);
        }
        __syncthreads();
    }

    // ---- epilogue ----
    // thread owns rows m0+wm+mt*16+lr (+8), cols c0+wn+nt*8+2*lc (+1)
    #pragma unroll
    for (int mt = 0; mt < 4; mt++) {
        #pragma unroll
        for (int half = 0; half < 2; half++) {
            const int m = m0 + wm + mt * 16 + half * 8 + lr;
            const int b = m >> 11, n = m & (NN - 1);
            #pragma unroll
            for (int nt = 0; nt < 4; nt++) {
                const int c = c0 + wn + nt * 8 + 2 * lc;
                const float v0 = acc[mt][nt][half * 2 + 0];
                const float v1 = acc[mt][nt][half * 2 + 1];
                if (mode == 3) {
                    float2 bv = *(const float2*)&bias[c];
                    *(float2*)&out[(size_t)m * DM + c] = make_float2(v0 + bv.x, v1 + bv.y);
                } else if (mode == 1) {
                    const int h = c >> 6, d = c & 63;
                    float* dst = g_Kt + ((size_t)(b * HH + h)) * DH * NN + n;
                    dst[(size_t)d * NN]       = v0;
                    dst[(size_t)(d + 1) * NN] = v1;
                } else {
                    const int h = c >> 6, d = c & 63;
                    float* dst = (mode == 0) ? g_Q : g_V;
                    *(float2*)&dst[(((size_t)(b * HH + h)) * NN + n) * DH + d] = make_float2(v0, v1);
                }
            }
        }
    }
}

// ---------------------------------------------------------------------------
// L2-normalize Q rows ([bh][n][d], warp per row of 64)
// ---------------------------------------------------------------------------
__global__ __launch_bounds__(256) void norm_q_rows()
{
    int w    = (blockIdx.x * 256 + threadIdx.x) >> 5;
    int lane = threadIdx.x & 31;
    float* p = g_Q + (size_t)w * DH;
    float a = p[lane], b = p[lane + 32];
    float ss = a*a + b*b;
    #pragma unroll
    for (int off = 16; off; off >>= 1) ss += __shfl_xor_sync(0xffffffffu, ss, off);
    float sc = 1.0f / (sqrtf(ss) + EPSF);
    p[lane]      = a * sc;
    p[lane + 32] = b * sc;
}

// ---------------------------------------------------------------------------
// L2-normalize K columns ([bh][d][n], thread per n)
// ---------------------------------------------------------------------------
__global__ __launch_bounds__(256) void norm_k_cols()
{
    int gc = blockIdx.x * 256 + threadIdx.x;
    int bh = gc >> 11, n = gc & (NN-1);
    float* p = g_Kt + (size_t)bh * DH * NN + n;
    float v[DH];
    float ss = 0.f;
    #pragma unroll
    for (int d = 0; d < DH; d++) { v[d] = p[(size_t)d*NN]; ss += v[d]*v[d]; }
    float sc = 1.0f / (sqrtf(ss) + EPSF);
    #pragma unroll
    for (int d = 0; d < DH; d++) p[(size_t)d*NN] = v[d]*sc;
}

// ---------------------------------------------------------------------------
// Flash-style causal attention (R3 version; epilogue rounds to tf32)
// ---------------------------------------------------------------------------
__global__ __launch_bounds__(256) void attn_kernel()
{
    __shared__ float Qs[64*PAD];   // [q][d]
    __shared__ float KV[64*PAD];   // K stage: [d][j]; V stage: [j][d]
    const int tid  = threadIdx.x;
    const int qt   = blockIdx.x;
    const int bh   = blockIdx.y;
    const int qbase = qt * 64;
    const int lq   = tid >> 2;
    const int g    = tid & 3;
    const int lane = tid & 31;

    const float* Qp = g_Q  + (size_t)bh * NN * DH;
    const float* Kp = g_Kt + (size_t)bh * DH * NN;
    const float* Vp = g_V  + (size_t)bh * NN * DH;

    #pragma unroll
    for (int r = 0; r < 4; r++) {
        int idx = tid + 256*r;
        int q = idx >> 4, c4 = idx & 15;
        *(float4*)&Qs[q*PAD + c4*4] = *(const float4*)&Qp[(size_t)(qbase + q)*DH + c4*4];
    }

    float mrun = -INFINITY, lrun = 0.f;
    float acc[4][4] = {};

    for (int kt = 0; kt <= qt; kt++) {
        const int kbase = kt * 64;
        __syncthreads();
        #pragma unroll
        for (int r = 0; r < 4; r++) {          // K tile [d][j]
            int idx = tid + 256*r;
            int d = idx >> 4, c4 = idx & 15;
            *(float4*)&KV[d*PAD + c4*4] = *(const float4*)&Kp[(size_t)d*NN + kbase + c4*4];
        }
        __syncthreads();

        float s[4][4];
        #pragma unroll
        for (int u = 0; u < 4; u++) { s[u][0]=0.f; s[u][1]=0.f; s[u][2]=0.f; s[u][3]=0.f; }
        #pragma unroll 4
        for (int d = 0; d < 64; d++) {
            float qa = Qs[lq*PAD + d];
            #pragma unroll
            for (int u = 0; u < 4; u++) {
                float4 kv = *(const float4*)&KV[d*PAD + 16*u + 4*g];
                s[u][0] += qa*kv.x; s[u][1] += qa*kv.y; s[u][2] += qa*kv.z; s[u][3] += qa*kv.w;
            }
        }
        __syncthreads();
        #pragma unroll
        for (int r = 0; r < 4; r++) {          // V tile [j][d]
            int idx = tid + 256*r;
            int j = idx >> 4, c4 = idx & 15;
            *(float4*)&KV[j*PAD + c4*4] = *(const float4*)&Vp[(size_t)(kbase + j)*DH + c4*4];
        }

        const bool diag = (kt == qt);
        float tmax = -INFINITY;
        #pragma unroll
        for (int u = 0; u < 4; u++)
            #pragma unroll
            for (int v = 0; v < 4; v++) {
                float sv = s[u][v] * 0.125f;
                int j = 16*u + 4*g + v;
                if (diag && j > lq) sv = -INFINITY;
                s[u][v] = sv;
                tmax = fmaxf(tmax, sv);
            }
        tmax = fmaxf(tmax, __shfl_xor_sync(0xffffffffu, tmax, 1));
        tmax = fmaxf(tmax, __shfl_xor_sync(0xffffffffu, tmax, 2));
        float mnew = fmaxf(mrun, tmax);
        float corr = __expf(mrun - mnew);
        float tsum = 0.f;
        #pragma unroll
        for (int u = 0; u < 4; u++)
            #pragma unroll
            for (int v = 0; v < 4; v++) {
                float pp = __expf(s[u][v] - mnew);
                s[u][v] = pp;
                tsum += pp;
            }
        tsum += __shfl_xor_sync(0xffffffffu, tsum, 1);
        tsum += __shfl_xor_sync(0xffffffffu, tsum, 2);
        lrun = lrun*corr + tsum;
        mrun = mnew;
        #pragma unroll
        for (int u = 0; u < 4; u++) { acc[u][0]*=corr; acc[u][1]*=corr; acc[u][2]*=corr; acc[u][3]*=corr; }

        __syncthreads();

        #pragma unroll
        for (int u = 0; u < 4; u++)
            #pragma unroll
            for (int gg = 0; gg < 4; gg++)
                #pragma unroll
                for (int v = 0; v < 4; v++) {
                    int j = 16*u + 4*gg + v;
                    float p = __shfl_sync(0xffffffffu, s[u][v], (lane & ~3) | gg);
                    #pragma unroll
                    for (int uu = 0; uu < 4; uu++) {
                        float4 v4 = *(const float4*)&KV[j*PAD + 16*uu + 4*g];
                        acc[uu][0] += p*v4.x; acc[uu][1] += p*v4.y;
                        acc[uu][2] += p*v4.z; acc[uu][3] += p*v4.w;
                    }
                }
    }

    float inv = 1.0f / lrun;
    float* Op = g_O + (size_t)bh * NN * DH + (size_t)(qbase + lq) * DH;
    #pragma unroll
    for (int u = 0; u < 4; u++) {
        float4 o = make_float4(tf32r(acc[u][0]*inv), tf32r(acc[u][1]*inv),
                               tf32r(acc[u][2]*inv), tf32r(acc[u][3]*inv));
        *(float4*)&Op[16*u + 4*g] = o;
    }
}

// ---------------------------------------------------------------------------
extern "C" void kernel_launch(void* const* d_in, const int* in_sizes, int n_in,
                              void* d_out, int out_size)
{
    const float* X  = (const float*)d_in[0];
    const float* Wq = (const float*)d_in[1];
    const float* Wk = (const float*)d_in[2];
    const float* Wv = (const float*)d_in[3];
    const float* Wo = (const float*)d_in[4];
    const float* bo = (const float*)d_in[5];
    float* out = (float*)d_out;

    cudaFuncSetAttribute(gemm_tc, cudaFuncAttributeMaxDynamicSharedMemorySize, GEMM_SMEM);

    round_x<<<(MM*DM)/(4*256), 256>>>(X);
    dim3 tb(32, 8), tg(32, 32);
    transpose_w<<<tg, tb>>>(Wq, 0);
    transpose_w<<<tg, tb>>>(Wk, 1);
    transpose_w<<<tg, tb>>>(Wv, 2);
    transpose_w<<<tg, tb>>>(Wo, 3);

    // IMPORTANT: __device__ symbols must be resolved to device addresses here.
    // Passing the symbol name directly from host code hands the kernel the
    // host-side shadow address (which GB300's ATS happily reads as zeros).
    float* wt = nullptr;
    cudaGetSymbolAddress((void**)&wt, g_Wt);
    float* xr = nullptr;
    cudaGetSymbolAddress((void**)&xr, g_Xr);

    dim3 gg(DM/128, MM/128);   // (8, 32)
    gemm_tc<<<gg, 256, GEMM_SMEM>>>(xr, wt + 0*(size_t)DM*DM, nullptr, nullptr, 0);
    gemm_tc<<<gg, 256, GEMM_SMEM>>>(xr, wt + 1*(size_t)DM*DM, nullptr, nullptr, 1);
    gemm_tc<<<gg, 256, GEMM_SMEM>>>(xr, wt + 2*(size_t)DM*DM, nullptr, nullptr, 2);

    norm_q_rows<<<(BH*NN)/8, 256>>>();
    norm_k_cols<<<(BH*NN)/256, 256>>>();

    attn_kernel<<<dim3(NN/64, BH), 256>>>();

    gemm_tc<<<gg, 256, GEMM_SMEM>>>(nullptr, wt + 3*(size_t)DM*DM, bo, out, 3);
}

// round 8
// speedup vs baseline: 4.3338x; 2.1574x over previous
#include <cuda_runtime.h>
#include <cstdint>
#include <math.h>

#define BB 2
#define NN 2048
#define DM 1024
#define HH 16
#define DH 64
#define MM (BB*NN)      /* 4096 */
#define BH (BB*HH)      /* 32   */
#define EPSF 1e-6f

// ---------------- device scratch (no allocation allowed) -------------------
__device__ float g_Q [BH*NN*DH];     // [bh][n][d]  normalized Q (tf32-rounded, pre-scale NOT applied)
__device__ float g_Kt[BH*DH*NN];     // [bh][d][n]  normalized K, transposed (tf32-rounded)
__device__ float g_V [BH*NN*DH];     // [bh][n][d]  (tf32-rounded)
__device__ float g_O [BH*NN*DH];     // [bh][n][d]  attention out (tf32-rounded)
__device__ float g_Wt[4*DM*DM];      // W^T for Wq,Wk,Wv,Wo (tf32-rounded)
__device__ float g_Xr[MM*DM];        // X rounded to tf32

// ---------------- helpers ---------------------------------------------------
__device__ __forceinline__ float tf32r(float x) {
    float y; asm("cvt.rna.tf32.f32 %0, %1;" : "=f"(y) : "f"(x)); return y;
}
__device__ __forceinline__ void cp16(uint32_t dst, const void* src) {
    asm volatile("cp.async.cg.shared.global [%0], [%1], 16;" :: "r"(dst), "l"(src));
}
__device__ __forceinline__ void cp_commit() { asm volatile("cp.async.commit_group;"); }
template<int N> __device__ __forceinline__ void cp_wait() {
    asm volatile("cp.async.wait_group %0;" :: "n"(N));
}
__device__ __forceinline__ uint32_t smem_u32(const void* p) {
    uint32_t a;
    asm("{ .reg .u64 t; cvta.to.shared.u64 t, %1; cvt.u32.u64 %0, t; }" : "=r"(a) : "l"(p));
    return a;
}
__device__ __forceinline__ void mma_tf32(float* c, const uint32_t* a, const uint32_t* b) {
    asm volatile(
        "mma.sync.aligned.m16n8k8.row.col.f32.tf32.tf32.f32 "
        "{%0,%1,%2,%3}, {%4,%5,%6,%7}, {%8,%9}, {%0,%1,%2,%3};"
        : "+f"(c[0]), "+f"(c[1]), "+f"(c[2]), "+f"(c[3])
        : "r"(a[0]), "r"(a[1]), "r"(a[2]), "r"(a[3]), "r"(b[0]), "r"(b[1]));
}

// ---------------------------------------------------------------------------
// Pre-passes: round X to tf32; transpose + round weights
// ---------------------------------------------------------------------------
__global__ __launch_bounds__(256) void round_x(const float* __restrict__ X)
{
    int i = blockIdx.x * 256 + threadIdx.x;
    float4 v = ((const float4*)X)[i];
    v.x = tf32r(v.x); v.y = tf32r(v.y); v.z = tf32r(v.z); v.w = tf32r(v.w);
    ((float4*)g_Xr)[i] = v;
}

__global__ __launch_bounds__(256) void transpose_w(const float* __restrict__ W, int slot)
{
    __shared__ float ts[32][33];
    float* Wt = g_Wt + (size_t)slot * DM * DM;
    int bx = blockIdx.x * 32, by = blockIdx.y * 32;
    #pragma unroll
    for (int i = 0; i < 32; i += 8)
        ts[threadIdx.y + i][threadIdx.x] = W[(size_t)(by + threadIdx.y + i) * DM + bx + threadIdx.x];
    __syncthreads();
    #pragma unroll
    for (int i = 0; i < 32; i += 8)
        Wt[(size_t)(bx + threadIdx.y + i) * DM + by + threadIdx.x] = tf32r(ts[threadIdx.x][threadIdx.y + i]);
}

// ---------------------------------------------------------------------------
// mma.sync tf32 GEMM: C[4096 x 1024] = A @ Bt^T   (Bt is [n][k])
// BM=128 BN=128 BK=32, 256 threads = 8 warps (2 x 4), warp tile 64 x 32.
// mode 0: Q heads layout   1: Kt transposed   2: V heads layout (tf32-rounded)
// mode 3: out = D + bo (A gathered from g_O heads layout)
// ---------------------------------------------------------------------------
#define BK 32
#define LDS_ROW 36
#define TILE_F (128*LDS_ROW)
#define GEMM_SMEM (4*TILE_F*4)
#define KTILES (DM/BK)

__global__ __launch_bounds__(256, 1) void gemm_tc(
    const float* __restrict__ A, const float* __restrict__ Bt,
    const float* __restrict__ bias, float* __restrict__ out, int mode)
{
    extern __shared__ float sm[];
    float* sA[2] = { sm,            sm + 2*TILE_F };
    float* sB[2] = { sm + TILE_F,   sm + 3*TILE_F };

    const int tid  = threadIdx.x;
    const int wid  = tid >> 5;
    const int lane = tid & 31;
    const int lr   = lane >> 2;
    const int lc   = lane & 3;
    const int wm   = (wid & 1) * 64;
    const int wn   = (wid >> 1) * 32;
    const int m0   = blockIdx.y * 128;
    const int c0   = blockIdx.x * 128;

    const int lrow = tid >> 1, lhalf = tid & 1;
    const int am = m0 + lrow;
    const int ab = am >> 11, an = am & (NN - 1);
    const float* brow_base = Bt + (size_t)(c0 + lrow) * DM;
    const uint32_t sa_u[2] = { smem_u32(sA[0]), smem_u32(sA[1]) };
    const uint32_t sb_u[2] = { smem_u32(sB[0]), smem_u32(sB[1]) };
    const uint32_t dst_off = (uint32_t)lrow * (LDS_ROW*4) + (uint32_t)lhalf * 64;

    auto load_tile = [&](int t, int buf) {
        const int k0 = t * BK + lhalf * 16;
        const float* arow;
        if (mode == 3) {
            arow = g_O + ((size_t)(ab * HH + (k0 >> 6)) * NN + an) * DH + (k0 & 63);
        } else {
            arow = A + (size_t)am * DM + k0;
        }
        const float* brow = brow_base + k0;
        #pragma unroll
        for (int f = 0; f < 4; f++) {
            cp16(sa_u[buf] + dst_off + f * 16, arow + f * 4);
            cp16(sb_u[buf] + dst_off + f * 16, brow + f * 4);
        }
    };

    float acc[4][4][4] = {};

    load_tile(0, 0);
    cp_commit();

    for (int t = 0; t < KTILES; t++) {
        const int p = t & 1;
        if (t + 1 < KTILES) {
            load_tile(t + 1, 1 - p);
            cp_commit();
            cp_wait<1>();
        } else {
            cp_wait<0>();
        }
        __syncthreads();

        const float* Ab = sA[p];
        const float* Bb = sB[p];
        #pragma unroll
        for (int kk = 0; kk < 4; kk++) {
            const int k0 = kk * 8;
            uint32_t af[4][4], bf[4][2];
            #pragma unroll
            for (int mt = 0; mt < 4; mt++) {
                const int rb = wm + mt * 16;
                af[mt][0] = __float_as_uint(Ab[(rb +     lr) * LDS_ROW + k0 +     lc]);
                af[mt][1] = __float_as_uint(Ab[(rb + 8 + lr) * LDS_ROW + k0 +     lc]);
                af[mt][2] = __float_as_uint(Ab[(rb +     lr) * LDS_ROW + k0 + 4 + lc]);
                af[mt][3] = __float_as_uint(Ab[(rb + 8 + lr) * LDS_ROW + k0 + 4 + lc]);
            }
            #pragma unroll
            for (int nt = 0; nt < 4; nt++) {
                const int cb = wn + nt * 8;
                bf[nt][0] = __float_as_uint(Bb[(cb + lr) * LDS_ROW + k0 +     lc]);
                bf[nt][1] = __float_as_uint(Bb[(cb + lr) * LDS_ROW + k0 + 4 + lc]);
            }
            #pragma unroll
            for (int mt = 0; mt < 4; mt++)
                #pragma unroll
                for (int nt = 0; nt < 4; nt++)
                    mma_tf32(acc[mt][nt], af[mt], bf[nt]);
        }
        __syncthreads();
    }

    #pragma unroll
    for (int mt = 0; mt < 4; mt++) {
        #pragma unroll
        for (int half = 0; half < 2; half++) {
            const int m = m0 + wm + mt * 16 + half * 8 + lr;
            const int b = m >> 11, n = m & (NN - 1);
            #pragma unroll
            for (int nt = 0; nt < 4; nt++) {
                const int c = c0 + wn + nt * 8 + 2 * lc;
                const float v0 = acc[mt][nt][half * 2 + 0];
                const float v1 = acc[mt][nt][half * 2 + 1];
                if (mode == 3) {
                    float2 bv = *(const float2*)&bias[c];
                    *(float2*)&out[(size_t)m * DM + c] = make_float2(v0 + bv.x, v1 + bv.y);
                } else if (mode == 1) {
                    const int h = c >> 6, d = c & 63;
                    float* dst = g_Kt + ((size_t)(b * HH + h)) * DH * NN + n;
                    dst[(size_t)d * NN]       = v0;
                    dst[(size_t)(d + 1) * NN] = v1;
                } else if (mode == 2) {
                    const int h = c >> 6, d = c & 63;
                    *(float2*)&g_V[(((size_t)(b * HH + h)) * NN + n) * DH + d] =
                        make_float2(tf32r(v0), tf32r(v1));
                } else {
                    const int h = c >> 6, d = c & 63;
                    *(float2*)&g_Q[(((size_t)(b * HH + h)) * NN + n) * DH + d] = make_float2(v0, v1);
                }
            }
        }
    }
}

// ---------------------------------------------------------------------------
// L2-normalize Q rows (rounds to tf32)
// ---------------------------------------------------------------------------
__global__ __launch_bounds__(256) void norm_q_rows()
{
    int w    = (blockIdx.x * 256 + threadIdx.x) >> 5;
    int lane = threadIdx.x & 31;
    float* p = g_Q + (size_t)w * DH;
    float a = p[lane], b = p[lane + 32];
    float ss = a*a + b*b;
    #pragma unroll
    for (int off = 16; off; off >>= 1) ss += __shfl_xor_sync(0xffffffffu, ss, off);
    float sc = 1.0f / (sqrtf(ss) + EPSF);
    p[lane]      = tf32r(a * sc);
    p[lane + 32] = tf32r(b * sc);
}

// ---------------------------------------------------------------------------
// L2-normalize K columns (rounds to tf32)
// ---------------------------------------------------------------------------
__global__ __launch_bounds__(256) void norm_k_cols()
{
    int gc = blockIdx.x * 256 + threadIdx.x;
    int bh = gc >> 11, n = gc & (NN-1);
    float* p = g_Kt + (size_t)bh * DH * NN + n;
    float v[DH];
    float ss = 0.f;
    #pragma unroll
    for (int d = 0; d < DH; d++) { v[d] = p[(size_t)d*NN]; ss += v[d]*v[d]; }
    float sc = 1.0f / (sqrtf(ss) + EPSF);
    #pragma unroll
    for (int d = 0; d < DH; d++) p[(size_t)d*NN] = tf32r(v[d]*sc);
}

// ---------------------------------------------------------------------------
// Tensor-core flash attention.
// Block = 128 queries of one (b,h); 8 warps; warp = rows 16w..16w+15.
// K/V tiles of 64 keys, cp.async double-buffered.
// KROW=72 -> conflict-free B-frag LDS; PROW=68 -> conflict-free A-frag LDS.
// ---------------------------------------------------------------------------
#define KROW 72
#define PROW 68
#define KV_F (64*KROW)                       /* floats per K (or V) buffer */
#define AT_SMEM ((4*KV_F + 128*PROW)*4)      /* 108544 bytes */

__global__ __launch_bounds__(256, 1) void attn_tc()
{
    extern __shared__ float sm[];
    float* Ks[2] = { sm,          sm + 2*KV_F };
    float* Vs[2] = { sm + KV_F,   sm + 3*KV_F };
    float* Ps    = sm + 4*KV_F;

    const int tid  = threadIdx.x;
    const int wid  = tid >> 5;
    const int lane = tid & 31;
    const int lr   = lane >> 2;              // 0..7
    const int lc   = lane & 3;               // 0..3
    const int qt   = gridDim.x - 1 - blockIdx.x;   // heavy blocks first
    const int bh   = blockIdx.y;
    const int qbase = qt * 128;
    const int T    = 2 * qt + 2;             // 64-key tiles

    const float* Qp = g_Q  + (size_t)bh * NN * DH;
    const float* Kp = g_Kt + (size_t)bh * DH * NN;
    const float* Vp = g_V  + (size_t)bh * NN * DH;

    const uint32_t ks_u[2] = { smem_u32(Ks[0]), smem_u32(Ks[1]) };
    const uint32_t vs_u[2] = { smem_u32(Vs[0]), smem_u32(Vs[1]) };
    const int ldrow = tid >> 2, ldseg = tid & 3;

    auto load_kv = [&](int t, int buf) {
        const int kbase = t * 64;
        const float* ksrc = Kp + (size_t)ldrow * NN + kbase + ldseg * 16;
        const float* vsrc = Vp + (size_t)(kbase + ldrow) * DH + ldseg * 16;
        const uint32_t doff = (uint32_t)ldrow * (KROW*4) + (uint32_t)ldseg * 64;
        #pragma unroll
        for (int f = 0; f < 4; f++) {
            cp16(ks_u[buf] + doff + f * 16, ksrc + f * 4);
            cp16(vs_u[buf] + doff + f * 16, vsrc + f * 4);
        }
    };

    load_kv(0, 0);
    cp_commit();

    // ---- stage Q into Ps, build A-fragments (pre-scaled by 1/8) ----
    {
        const int row = tid >> 1, halfq = tid & 1;
        const float4* src = (const float4*)(Qp + (size_t)(qbase + row) * DH + halfq * 32);
        float4* dst = (float4*)(Ps + row * PROW + halfq * 32);
        #pragma unroll
        for (int f = 0; f < 8; f++) dst[f] = src[f];
    }
    __syncthreads();
    uint32_t aq[8][4];
    {
        const float* q0 = Ps + (16 * wid +     lr) * PROW;
        const float* q1 = Ps + (16 * wid + 8 + lr) * PROW;
        #pragma unroll
        for (int k8 = 0; k8 < 8; k8++) {
            aq[k8][0] = __float_as_uint(q0[8*k8 +     lc] * 0.125f);
            aq[k8][1] = __float_as_uint(q1[8*k8 +     lc] * 0.125f);
            aq[k8][2] = __float_as_uint(q0[8*k8 + 4 + lc] * 0.125f);
            aq[k8][3] = __float_as_uint(q1[8*k8 + 4 + lc] * 0.125f);
        }
    }

    float m0r = -INFINITY, m1r = -INFINITY, l0 = 0.f, l1 = 0.f;
    float o[8][4] = {};
    const int q0row = qbase + 16 * wid + lr;
    const int q1row = q0row + 8;

    for (int t = 0; t < T; t++) {
        const int p = t & 1;
        __syncthreads();                       // all warps done with buf 1-p (tile t-1) + Q staging
        if (t + 1 < T) {
            load_kv(t + 1, 1 - p);
            cp_commit();
            cp_wait<1>();
        } else {
            cp_wait<0>();
        }
        __syncthreads();                       // tile t resident

        // ---- S = Q K^T (scaled) ----
        float s[8][4] = {};
        const float* Kb = Ks[p];
        #pragma unroll
        for (int k8 = 0; k8 < 8; k8++) {
            uint32_t bk[8][2];
            const float* kr0 = Kb + (8*k8 +     lc) * KROW;
            const float* kr1 = Kb + (8*k8 + 4 + lc) * KROW;
            #pragma unroll
            for (int nt = 0; nt < 8; nt++) {
                bk[nt][0] = __float_as_uint(kr0[8*nt + lr]);
                bk[nt][1] = __float_as_uint(kr1[8*nt + lr]);
            }
            #pragma unroll
            for (int nt = 0; nt < 8; nt++)
                mma_tf32(s[nt], aq[k8], bk[nt]);
        }

        // ---- online softmax on C-fragments ----
        const int kbase = t * 64;
        const bool diag = (t >= T - 2);
        float mx0 = -INFINITY, mx1 = -INFINITY;
        #pragma unroll
        for (int nt = 0; nt < 8; nt++) {
            #pragma unroll
            for (int c = 0; c < 2; c++) {
                if (diag) {
                    const int j = kbase + 8*nt + 2*lc + c;
                    if (j > q0row) s[nt][c]     = -INFINITY;
                    if (j > q1row) s[nt][2 + c] = -INFINITY;
                }
                mx0 = fmaxf(mx0, s[nt][c]);
                mx1 = fmaxf(mx1, s[nt][2 + c]);
            }
        }
        mx0 = fmaxf(mx0, __shfl_xor_sync(0xffffffffu, mx0, 1));
        mx0 = fmaxf(mx0, __shfl_xor_sync(0xffffffffu, mx0, 2));
        mx1 = fmaxf(mx1, __shfl_xor_sync(0xffffffffu, mx1, 1));
        mx1 = fmaxf(mx1, __shfl_xor_sync(0xffffffffu, mx1, 2));
        const float mn0 = fmaxf(m0r, mx0), mn1 = fmaxf(m1r, mx1);
        const float cr0 = __expf(m0r - mn0), cr1 = __expf(m1r - mn1);
        float sum0 = 0.f, sum1 = 0.f;
        #pragma unroll
        for (int nt = 0; nt < 8; nt++) {
            #pragma unroll
            for (int c = 0; c < 2; c++) {
                float p0 = tf32r(__expf(s[nt][c]     - mn0));
                float p1 = tf32r(__expf(s[nt][2 + c] - mn1));
                s[nt][c] = p0;  s[nt][2 + c] = p1;
                sum0 += p0; sum1 += p1;
            }
        }
        sum0 += __shfl_xor_sync(0xffffffffu, sum0, 1);
        sum0 += __shfl_xor_sync(0xffffffffu, sum0, 2);
        sum1 += __shfl_xor_sync(0xffffffffu, sum1, 1);
        sum1 += __shfl_xor_sync(0xffffffffu, sum1, 2);
        l0 = l0 * cr0 + sum0;  m0r = mn0;
        l1 = l1 * cr1 + sum1;  m1r = mn1;
        #pragma unroll
        for (int nt = 0; nt < 8; nt++) {
            o[nt][0] *= cr0; o[nt][1] *= cr0;
            o[nt][2] *= cr1; o[nt][3] *= cr1;
        }

        // ---- P -> smem (warp-private rows), reload as A-fragments ----
        {
            float* pr0 = Ps + (16 * wid +     lr) * PROW + 2 * lc;
            float* pr1 = Ps + (16 * wid + 8 + lr) * PROW + 2 * lc;
            #pragma unroll
            for (int nt = 0; nt < 8; nt++) {
                *(float2*)(pr0 + 8*nt) = make_float2(s[nt][0], s[nt][1]);
                *(float2*)(pr1 + 8*nt) = make_float2(s[nt][2], s[nt][3]);
            }
        }
        __syncwarp();

        // ---- O += P V ----
        const float* Vb = Vs[p];
        const float* pr0 = Ps + (16 * wid +     lr) * PROW;
        const float* pr1 = Ps + (16 * wid + 8 + lr) * PROW;
        #pragma unroll
        for (int jt = 0; jt < 8; jt++) {
            uint32_t ap[4];
            ap[0] = __float_as_uint(pr0[8*jt +     lc]);
            ap[1] = __float_as_uint(pr1[8*jt +     lc]);
            ap[2] = __float_as_uint(pr0[8*jt + 4 + lc]);
            ap[3] = __float_as_uint(pr1[8*jt + 4 + lc]);
            uint32_t bv[8][2];
            const float* vr0 = Vb + (8*jt +     lc) * KROW;
            const float* vr1 = Vb + (8*jt + 4 + lc) * KROW;
            #pragma unroll
            for (int nt = 0; nt < 8; nt++) {
                bv[nt][0] = __float_as_uint(vr0[8*nt + lr]);
                bv[nt][1] = __float_as_uint(vr1[8*nt + lr]);
            }
            #pragma unroll
            for (int nt = 0; nt < 8; nt++)
                mma_tf32(o[nt], ap, bv[nt]);
        }
    }

    // ---- epilogue: O /= l, round to tf32, write heads layout ----
    const float inv0 = 1.0f / l0, inv1 = 1.0f / l1;
    float* Op = g_O + (size_t)bh * NN * DH;
    float* o0 = Op + (size_t)q0row * DH + 2 * lc;
    float* o1 = Op + (size_t)q1row * DH + 2 * lc;
    #pragma unroll
    for (int nt = 0; nt < 8; nt++) {
        *(float2*)(o0 + 8*nt) = make_float2(tf32r(o[nt][0] * inv0), tf32r(o[nt][1] * inv0));
        *(float2*)(o1 + 8*nt) = make_float2(tf32r(o[nt][2] * inv1), tf32r(o[nt][3] * inv1));
    }
}

// ---------------------------------------------------------------------------
extern "C" void kernel_launch(void* const* d_in, const int* in_sizes, int n_in,
                              void* d_out, int out_size)
{
    const float* X  = (const float*)d_in[0];
    const float* Wq = (const float*)d_in[1];
    const float* Wk = (const float*)d_in[2];
    const float* Wv = (const float*)d_in[3];
    const float* Wo = (const float*)d_in[4];
    const float* bo = (const float*)d_in[5];
    float* out = (float*)d_out;

    cudaFuncSetAttribute(gemm_tc, cudaFuncAttributeMaxDynamicSharedMemorySize, GEMM_SMEM);
    cudaFuncSetAttribute(attn_tc, cudaFuncAttributeMaxDynamicSharedMemorySize, AT_SMEM);

    round_x<<<(MM*DM)/(4*256), 256>>>(X);
    dim3 tb(32, 8), tg(32, 32);
    transpose_w<<<tg, tb>>>(Wq, 0);
    transpose_w<<<tg, tb>>>(Wk, 1);
    transpose_w<<<tg, tb>>>(Wv, 2);
    transpose_w<<<tg, tb>>>(Wo, 3);

    // __device__ symbols must be resolved to device addresses host-side.
    float* wt = nullptr;
    cudaGetSymbolAddress((void**)&wt, g_Wt);
    float* xr = nullptr;
    cudaGetSymbolAddress((void**)&xr, g_Xr);

    dim3 gg(DM/128, MM/128);   // (8, 32)
    gemm_tc<<<gg, 256, GEMM_SMEM>>>(xr, wt + 0*(size_t)DM*DM, nullptr, nullptr, 0);
    gemm_tc<<<gg, 256, GEMM_SMEM>>>(xr, wt + 1*(size_t)DM*DM, nullptr, nullptr, 1);
    gemm_tc<<<gg, 256, GEMM_SMEM>>>(xr, wt + 2*(size_t)DM*DM, nullptr, nullptr, 2);

    norm_q_rows<<<(BH*NN)/8, 256>>>();
    norm_k_cols<<<(BH*NN)/256, 256>>>();

    attn_tc<<<dim3(NN/128, BH), 256, AT_SMEM>>>();

    gemm_tc<<<gg, 256, GEMM_SMEM>>>(nullptr, wt + 3*(size_t)DM*DM, bo, out, 3);
}

// round 10
// speedup vs baseline: 4.8214x; 1.1125x over previous
#include <cuda_runtime.h>
#include <cstdint>
#include <math.h>

#define BB 2
#define NN 2048
#define DM 1024
#define HH 16
#define DH 64
#define MM (BB*NN)      /* 4096 */
#define BH (BB*HH)      /* 32   */
#define EPSF 1e-6f

// ---------------- device scratch (no allocation allowed) -------------------
__device__ float g_Q [BH*NN*DH];     // [bh][n][d]  normalized Q (tf32-rounded)
__device__ float g_Kt[BH*DH*NN];     // [bh][d][n]  normalized K, transposed (tf32-rounded)
__device__ float g_V [BH*NN*DH];     // [bh][n][d]  (tf32-rounded)
__device__ float g_O [BH*NN*DH];     // [bh][n][d]  attention out (tf32-rounded)
__device__ float g_Wt[4*DM*DM];      // W^T for Wq,Wk,Wv,Wo (tf32-rounded)
__device__ float g_Xr[MM*DM];        // X rounded to tf32

// ---------------- helpers ---------------------------------------------------
__device__ __forceinline__ float tf32r(float x) {
    float y; asm("cvt.rna.tf32.f32 %0, %1;" : "=f"(y) : "f"(x)); return y;
}
__device__ __forceinline__ void cp16(uint32_t dst, const void* src) {
    asm volatile("cp.async.cg.shared.global [%0], [%1], 16;" :: "r"(dst), "l"(src));
}
__device__ __forceinline__ void cp_commit() { asm volatile("cp.async.commit_group;"); }
template<int N> __device__ __forceinline__ void cp_wait() {
    asm volatile("cp.async.wait_group %0;" :: "n"(N));
}
__device__ __forceinline__ uint32_t smem_u32(const void* p) {
    uint32_t a;
    asm("{ .reg .u64 t; cvta.to.shared.u64 t, %1; cvt.u32.u64 %0, t; }" : "=r"(a) : "l"(p));
    return a;
}
__device__ __forceinline__ void mma_tf32(float* c, const uint32_t* a, const uint32_t* b) {
    asm volatile(
        "mma.sync.aligned.m16n8k8.row.col.f32.tf32.tf32.f32 "
        "{%0,%1,%2,%3}, {%4,%5,%6,%7}, {%8,%9}, {%0,%1,%2,%3};"
        : "+f"(c[0]), "+f"(c[1]), "+f"(c[2]), "+f"(c[3])
        : "r"(a[0]), "r"(a[1]), "r"(a[2]), "r"(a[3]), "r"(b[0]), "r"(b[1]));
}

// ---------------------------------------------------------------------------
// Pre-passes: round X to tf32; transpose + round weights
// ---------------------------------------------------------------------------
__global__ __launch_bounds__(256) void round_x(const float* __restrict__ X)
{
    int i = blockIdx.x * 256 + threadIdx.x;
    float4 v = ((const float4*)X)[i];
    v.x = tf32r(v.x); v.y = tf32r(v.y); v.z = tf32r(v.z); v.w = tf32r(v.w);
    ((float4*)g_Xr)[i] = v;
}

__global__ __launch_bounds__(256) void transpose_w(const float* __restrict__ W, int slot)
{
    __shared__ float ts[32][33];
    float* Wt = g_Wt + (size_t)slot * DM * DM;
    int bx = blockIdx.x * 32, by = blockIdx.y * 32;
    #pragma unroll
    for (int i = 0; i < 32; i += 8)
        ts[threadIdx.y + i][threadIdx.x] = W[(size_t)(by + threadIdx.y + i) * DM + bx + threadIdx.x];
    __syncthreads();
    #pragma unroll
    for (int i = 0; i < 32; i += 8)
        Wt[(size_t)(bx + threadIdx.y + i) * DM + by + threadIdx.x] = tf32r(ts[threadIdx.x][threadIdx.y + i]);
}

// ---------------------------------------------------------------------------
// mma.sync tf32 GEMM: C[4096 x 1024] = A @ Bt^T   (Bt is [n][k])
// BM=128 BN=128 BK=32, 256 threads = 8 warps (2 x 4), warp tile 64 x 32.
// __launch_bounds__(256,2): cap regs at 128 so 2 CTAs/SM co-reside.
// ---------------------------------------------------------------------------
#define BK 32
#define LDS_ROW 36
#define TILE_F (128*LDS_ROW)
#define GEMM_SMEM (4*TILE_F*4)
#define KTILES (DM/BK)

__global__ __launch_bounds__(256, 2) void gemm_tc(
    const float* __restrict__ A, const float* __restrict__ Bt,
    const float* __restrict__ bias, float* __restrict__ out, int mode)
{
    extern __shared__ float sm[];
    float* sA[2] = { sm,            sm + 2*TILE_F };
    float* sB[2] = { sm + TILE_F,   sm + 3*TILE_F };

    const int tid  = threadIdx.x;
    const int wid  = tid >> 5;
    const int lane = tid & 31;
    const int lr   = lane >> 2;
    const int lc   = lane & 3;
    const int wm   = (wid & 1) * 64;
    const int wn   = (wid >> 1) * 32;
    const int m0   = blockIdx.y * 128;
    const int c0   = blockIdx.x * 128;

    const int lrow = tid >> 1, lhalf = tid & 1;
    const int am = m0 + lrow;
    const int ab = am >> 11, an = am & (NN - 1);
    const float* brow_base = Bt + (size_t)(c0 + lrow) * DM;
    const uint32_t sa_u[2] = { smem_u32(sA[0]), smem_u32(sA[1]) };
    const uint32_t sb_u[2] = { smem_u32(sB[0]), smem_u32(sB[1]) };
    const uint32_t dst_off = (uint32_t)lrow * (LDS_ROW*4) + (uint32_t)lhalf * 64;

    auto load_tile = [&](int t, int buf) {
        const int k0 = t * BK + lhalf * 16;
        const float* arow;
        if (mode == 3) {
            arow = g_O + ((size_t)(ab * HH + (k0 >> 6)) * NN + an) * DH + (k0 & 63);
        } else {
            arow = A + (size_t)am * DM + k0;
        }
        const float* brow = brow_base + k0;
        #pragma unroll
        for (int f = 0; f < 4; f++) {
            cp16(sa_u[buf] + dst_off + f * 16, arow + f * 4);
            cp16(sb_u[buf] + dst_off + f * 16, brow + f * 4);
        }
    };

    float acc[4][4][4] = {};

    load_tile(0, 0);
    cp_commit();

    for (int t = 0; t < KTILES; t++) {
        const int p = t & 1;
        if (t + 1 < KTILES) {
            load_tile(t + 1, 1 - p);
            cp_commit();
            cp_wait<1>();
        } else {
            cp_wait<0>();
        }
        __syncthreads();

        const float* Ab = sA[p];
        const float* Bb = sB[p];
        #pragma unroll
        for (int kk = 0; kk < 4; kk++) {
            const int k0 = kk * 8;
            uint32_t af[4][4], bf[4][2];
            #pragma unroll
            for (int mt = 0; mt < 4; mt++) {
                const int rb = wm + mt * 16;
                af[mt][0] = __float_as_uint(Ab[(rb +     lr) * LDS_ROW + k0 +     lc]);
                af[mt][1] = __float_as_uint(Ab[(rb + 8 + lr) * LDS_ROW + k0 +     lc]);
                af[mt][2] = __float_as_uint(Ab[(rb +     lr) * LDS_ROW + k0 + 4 + lc]);
                af[mt][3] = __float_as_uint(Ab[(rb + 8 + lr) * LDS_ROW + k0 + 4 + lc]);
            }
            #pragma unroll
            for (int nt = 0; nt < 4; nt++) {
                const int cb = wn + nt * 8;
                bf[nt][0] = __float_as_uint(Bb[(cb + lr) * LDS_ROW + k0 +     lc]);
                bf[nt][1] = __float_as_uint(Bb[(cb + lr) * LDS_ROW + k0 + 4 + lc]);
            }
            #pragma unroll
            for (int mt = 0; mt < 4; mt++)
                #pragma unroll
                for (int nt = 0; nt < 4; nt++)
                    mma_tf32(acc[mt][nt], af[mt], bf[nt]);
        }
        __syncthreads();
    }

    #pragma unroll
    for (int mt = 0; mt < 4; mt++) {
        #pragma unroll
        for (int half = 0; half < 2; half++) {
            const int m = m0 + wm + mt * 16 + half * 8 + lr;
            const int b = m >> 11, n = m & (NN - 1);
            #pragma unroll
            for (int nt = 0; nt < 4; nt++) {
                const int c = c0 + wn + nt * 8 + 2 * lc;
                const float v0 = acc[mt][nt][half * 2 + 0];
                const float v1 = acc[mt][nt][half * 2 + 1];
                if (mode == 3) {
                    float2 bv = *(const float2*)&bias[c];
                    *(float2*)&out[(size_t)m * DM + c] = make_float2(v0 + bv.x, v1 + bv.y);
                } else if (mode == 1) {
                    const int h = c >> 6, d = c & 63;
                    float* dst = g_Kt + ((size_t)(b * HH + h)) * DH * NN + n;
                    dst[(size_t)d * NN]       = v0;
                    dst[(size_t)(d + 1) * NN] = v1;
                } else if (mode == 2) {
                    const int h = c >> 6, d = c & 63;
                    *(float2*)&g_V[(((size_t)(b * HH + h)) * NN + n) * DH + d] =
                        make_float2(tf32r(v0), tf32r(v1));
                } else {
                    const int h = c >> 6, d = c & 63;
                    *(float2*)&g_Q[(((size_t)(b * HH + h)) * NN + n) * DH + d] = make_float2(v0, v1);
                }
            }
        }
    }
}

// ---------------------------------------------------------------------------
// L2-normalize Q rows (rounds to tf32)
// ---------------------------------------------------------------------------
__global__ __launch_bounds__(256) void norm_q_rows()
{
    int w    = (blockIdx.x * 256 + threadIdx.x) >> 5;
    int lane = threadIdx.x & 31;
    float* p = g_Q + (size_t)w * DH;
    float a = p[lane], b = p[lane + 32];
    float ss = a*a + b*b;
    #pragma unroll
    for (int off = 16; off; off >>= 1) ss += __shfl_xor_sync(0xffffffffu, ss, off);
    float sc = 1.0f / (sqrtf(ss) + EPSF);
    p[lane]      = tf32r(a * sc);
    p[lane + 32] = tf32r(b * sc);
}

// ---------------------------------------------------------------------------
// L2-normalize K columns (rounds to tf32)
// ---------------------------------------------------------------------------
__global__ __launch_bounds__(256) void norm_k_cols()
{
    int gc = blockIdx.x * 256 + threadIdx.x;
    int bh = gc >> 11, n = gc & (NN-1);
    float* p = g_Kt + (size_t)bh * DH * NN + n;
    float v[DH];
    float ss = 0.f;
    #pragma unroll
    for (int d = 0; d < DH; d++) { v[d] = p[(size_t)d*NN]; ss += v[d]*v[d]; }
    float sc = 1.0f / (sqrtf(ss) + EPSF);
    #pragma unroll
    for (int d = 0; d < DH; d++) p[(size_t)d*NN] = tf32r(v[d]*sc);
}

// ---------------------------------------------------------------------------
// Tensor-core flash attention, 2 CTAs/SM version.
// Block = 128 queries of one (b,h); 8 warps; warp = rows 16w..16w+15.
// K/V tiles of 64 keys double-buffered. Q staged (pre-scaled 1/8) in Qs smem,
// A-frags reloaded per tile (saves 32 persistent regs). P never touches smem:
// C-frag -> A-frag conversion via quad shuffles.
// smem = 4*64*72 + 128*68 floats = 108544 B -> 2 CTAs/SM; regs capped at 128.
// ---------------------------------------------------------------------------
#define KROW 72
#define QROW 68
#define KV_F (64*KROW)
#define AT_SMEM ((4*KV_F + 128*QROW)*4)      /* 108544 bytes */

__global__ __launch_bounds__(256, 2) void attn_tc()
{
    extern __shared__ float sm[];
    float* Ks[2] = { sm,          sm + 2*KV_F };
    float* Vs[2] = { sm + KV_F,   sm + 3*KV_F };
    float* Qs    = sm + 4*KV_F;

    const int tid  = threadIdx.x;
    const int wid  = tid >> 5;
    const int lane = tid & 31;
    const int lr   = lane >> 2;              // 0..7
    const int lc   = lane & 3;               // 0..3
    const int qt   = gridDim.x - 1 - blockIdx.x;   // heavy blocks first
    const int bh   = blockIdx.y;
    const int qbase = qt * 128;
    const int T    = 2 * qt + 2;             // 64-key tiles

    const float* Qp = g_Q  + (size_t)bh * NN * DH;
    const float* Kp = g_Kt + (size_t)bh * DH * NN;
    const float* Vp = g_V  + (size_t)bh * NN * DH;

    const uint32_t ks_u[2] = { smem_u32(Ks[0]), smem_u32(Ks[1]) };
    const uint32_t vs_u[2] = { smem_u32(Vs[0]), smem_u32(Vs[1]) };
    const int ldrow = tid >> 2, ldseg = tid & 3;

    auto load_kv = [&](int t, int buf) {
        const int kbase = t * 64;
        const float* ksrc = Kp + (size_t)ldrow * NN + kbase + ldseg * 16;
        const float* vsrc = Vp + (size_t)(kbase + ldrow) * DH + ldseg * 16;
        const uint32_t doff = (uint32_t)ldrow * (KROW*4) + (uint32_t)ldseg * 64;
        #pragma unroll
        for (int f = 0; f < 4; f++) {
            cp16(ks_u[buf] + doff + f * 16, ksrc + f * 4);
            cp16(vs_u[buf] + doff + f * 16, vsrc + f * 4);
        }
    };

    load_kv(0, 0);
    cp_commit();

    // ---- stage Q into Qs (pre-scaled by 1/8 = exact) ----
    {
        const int row = tid >> 1, halfq = tid & 1;
        const float4* src = (const float4*)(Qp + (size_t)(qbase + row) * DH + halfq * 32);
        float4* dst = (float4*)(Qs + row * QROW + halfq * 32);
        #pragma unroll
        for (int f = 0; f < 8; f++) {
            float4 v = src[f];
            dst[f] = make_float4(v.x * 0.125f, v.y * 0.125f, v.z * 0.125f, v.w * 0.125f);
        }
    }

    float m0r = -INFINITY, m1r = -INFINITY, l0 = 0.f, l1 = 0.f;
    float o[8][4] = {};
    const int q0row = qbase + 16 * wid + lr;
    const int q1row = q0row + 8;
    const float* q0 = Qs + (16 * wid +     lr) * QROW;
    const float* q1 = Qs + (16 * wid + 8 + lr) * QROW;

    for (int t = 0; t < T; t++) {
        const int p = t & 1;
        __syncthreads();                       // buf 1-p reads done (t=0: no-op sync)
        if (t + 1 < T) {
            load_kv(t + 1, 1 - p);
            cp_commit();
            cp_wait<1>();
        } else {
            cp_wait<0>();
        }
        __syncthreads();                       // tile t resident; Qs visible (t=0)

        // ---- S = Q K^T (scaled) ----
        float s[8][4] = {};
        const float* Kb = Ks[p];
        #pragma unroll
        for (int k8 = 0; k8 < 8; k8++) {
            uint32_t af[4];
            af[0] = __float_as_uint(q0[8*k8 +     lc]);
            af[1] = __float_as_uint(q1[8*k8 +     lc]);
            af[2] = __float_as_uint(q0[8*k8 + 4 + lc]);
            af[3] = __float_as_uint(q1[8*k8 + 4 + lc]);
            const float* kr0 = Kb + (8*k8 +     lc) * KROW;
            const float* kr1 = Kb + (8*k8 + 4 + lc) * KROW;
            #pragma unroll
            for (int hh = 0; hh < 2; hh++) {
                uint32_t bk[4][2];
                #pragma unroll
                for (int q = 0; q < 4; q++) {
                    const int nt = 4*hh + q;
                    bk[q][0] = __float_as_uint(kr0[8*nt + lr]);
                    bk[q][1] = __float_as_uint(kr1[8*nt + lr]);
                }
                #pragma unroll
                for (int q = 0; q < 4; q++)
                    mma_tf32(s[4*hh + q], af, bk[q]);
            }
        }

        // ---- online softmax on C-fragments ----
        const int kbase = t * 64;
        const bool diag = (t >= T - 2);
        float mx0 = -INFINITY, mx1 = -INFINITY;
        #pragma unroll
        for (int nt = 0; nt < 8; nt++) {
            #pragma unroll
            for (int c = 0; c < 2; c++) {
                if (diag) {
                    const int j = kbase + 8*nt + 2*lc + c;
                    if (j > q0row) s[nt][c]     = -INFINITY;
                    if (j > q1row) s[nt][2 + c] = -INFINITY;
                }
                mx0 = fmaxf(mx0, s[nt][c]);
                mx1 = fmaxf(mx1, s[nt][2 + c]);
            }
        }
        mx0 = fmaxf(mx0, __shfl_xor_sync(0xffffffffu, mx0, 1));
        mx0 = fmaxf(mx0, __shfl_xor_sync(0xffffffffu, mx0, 2));
        mx1 = fmaxf(mx1, __shfl_xor_sync(0xffffffffu, mx1, 1));
        mx1 = fmaxf(mx1, __shfl_xor_sync(0xffffffffu, mx1, 2));
        const float mn0 = fmaxf(m0r, mx0), mn1 = fmaxf(m1r, mx1);
        const float cr0 = __expf(m0r - mn0), cr1 = __expf(m1r - mn1);
        float sum0 = 0.f, sum1 = 0.f;
        #pragma unroll
        for (int nt = 0; nt < 8; nt++) {
            #pragma unroll
            for (int c = 0; c < 2; c++) {
                float p0 = tf32r(__expf(s[nt][c]     - mn0));
                float p1 = tf32r(__expf(s[nt][2 + c] - mn1));
                s[nt][c] = p0;  s[nt][2 + c] = p1;
                sum0 += p0; sum1 += p1;
            }
        }
        sum0 += __shfl_xor_sync(0xffffffffu, sum0, 1);
        sum0 += __shfl_xor_sync(0xffffffffu, sum0, 2);
        sum1 += __shfl_xor_sync(0xffffffffu, sum1, 1);
        sum1 += __shfl_xor_sync(0xffffffffu, sum1, 2);
        l0 = l0 * cr0 + sum0;  m0r = mn0;
        l1 = l1 * cr1 + sum1;  m1r = mn1;
        #pragma unroll
        for (int nt = 0; nt < 8; nt++) {
            o[nt][0] *= cr0; o[nt][1] *= cr0;
            o[nt][2] *= cr1; o[nt][3] *= cr1;
        }

        // ---- O += P V  (C-frag -> A-frag via quad shuffles) ----
        const float* Vb = Vs[p];
        const int qbase_lane = lane & ~3;
        const int src1 = qbase_lane | (lc >> 1);        // cols lc
        const int src2 = qbase_lane | (2 + (lc >> 1));  // cols lc+4
        const bool odd = (lc & 1);
        #pragma unroll
        for (int jt = 0; jt < 8; jt++) {
            uint32_t ap[4];
            {
                float a0 = __shfl_sync(0xffffffffu, s[jt][0], src1);
                float b0 = __shfl_sync(0xffffffffu, s[jt][1], src1);
                float a1 = __shfl_sync(0xffffffffu, s[jt][2], src1);
                float b1 = __shfl_sync(0xffffffffu, s[jt][3], src1);
                float a2 = __shfl_sync(0xffffffffu, s[jt][0], src2);
                float b2 = __shfl_sync(0xffffffffu, s[jt][1], src2);
                float a3 = __shfl_sync(0xffffffffu, s[jt][2], src2);
                float b3 = __shfl_sync(0xffffffffu, s[jt][3], src2);
                ap[0] = __float_as_uint(odd ? b0 : a0);
                ap[1] = __float_as_uint(odd ? b1 : a1);
                ap[2] = __float_as_uint(odd ? b2 : a2);
                ap[3] = __float_as_uint(odd ? b3 : a3);
            }
            const float* vr0 = Vb + (8*jt +     lc) * KROW;
            const float* vr1 = Vb + (8*jt + 4 + lc) * KROW;
            #pragma unroll
            for (int hh = 0; hh < 2; hh++) {
                uint32_t bv[4][2];
                #pragma unroll
                for (int q = 0; q < 4; q++) {
                    const int nt = 4*hh + q;
                    bv[q][0] = __float_as_uint(vr0[8*nt + lr]);
                    bv[q][1] = __float_as_uint(vr1[8*nt + lr]);
                }
                #pragma unroll
                for (int q = 0; q < 4; q++)
                    mma_tf32(o[4*hh + q], ap, bv[q]);
            }
        }
    }

    // ---- epilogue: O /= l, round to tf32, write heads layout ----
    const float inv0 = 1.0f / l0, inv1 = 1.0f / l1;
    float* Op = g_O + (size_t)bh * NN * DH;
    float* o0 = Op + (size_t)q0row * DH + 2 * lc;
    float* o1 = Op + (size_t)q1row * DH + 2 * lc;
    #pragma unroll
    for (int nt = 0; nt < 8; nt++) {
        *(float2*)(o0 + 8*nt) = make_float2(tf32r(o[nt][0] * inv0), tf32r(o[nt][1] * inv0));
        *(float2*)(o1 + 8*nt) = make_float2(tf32r(o[nt][2] * inv1), tf32r(o[nt][3] * inv1));
    }
}

// ---------------------------------------------------------------------------
extern "C" void kernel_launch(void* const* d_in, const int* in_sizes, int n_in,
                              void* d_out, int out_size)
{
    const float* X  = (const float*)d_in[0];
    const float* Wq = (const float*)d_in[1];
    const float* Wk = (const float*)d_in[2];
    const float* Wv = (const float*)d_in[3];
    const float* Wo = (const float*)d_in[4];
    const float* bo = (const float*)d_in[5];
    float* out = (float*)d_out;

    cudaFuncSetAttribute(gemm_tc, cudaFuncAttributeMaxDynamicSharedMemorySize, GEMM_SMEM);
    cudaFuncSetAttribute(attn_tc, cudaFuncAttributeMaxDynamicSharedMemorySize, AT_SMEM);

    round_x<<<(MM*DM)/(4*256), 256>>>(X);
    dim3 tb(32, 8), tg(32, 32);
    transpose_w<<<tg, tb>>>(Wq, 0);
    transpose_w<<<tg, tb>>>(Wk, 1);
    transpose_w<<<tg, tb>>>(Wv, 2);
    transpose_w<<<tg, tb>>>(Wo, 3);

    // __device__ symbols must be resolved to device addresses host-side.
    float* wt = nullptr;
    cudaGetSymbolAddress((void**)&wt, g_Wt);
    float* xr = nullptr;
    cudaGetSymbolAddress((void**)&xr, g_Xr);

    dim3 gg(DM/128, MM/128);   // (8, 32)
    gemm_tc<<<gg, 256, GEMM_SMEM>>>(xr, wt + 0*(size_t)DM*DM, nullptr, nullptr, 0);
    gemm_tc<<<gg, 256, GEMM_SMEM>>>(xr, wt + 1*(size_t)DM*DM, nullptr, nullptr, 1);
    gemm_tc<<<gg, 256, GEMM_SMEM>>>(xr, wt + 2*(size_t)DM*DM, nullptr, nullptr, 2);

    norm_q_rows<<<(BH*NN)/8, 256>>>();
    norm_k_cols<<<(BH*NN)/256, 256>>>();

    attn_tc<<<dim3(NN/128, BH), 256, AT_SMEM>>>();

    gemm_tc<<<gg, 256, GEMM_SMEM>>>(nullptr, wt + 3*(size_t)DM*DM, bo, out, 3);
}

// round 12
// speedup vs baseline: 4.9879x; 1.0345x over previous
#include <cuda_runtime.h>
#include <cstdint>
#include <math.h>

#define BB 2
#define NN 2048
#define DM 1024
#define HH 16
#define DH 64
#define MM (BB*NN)      /* 4096 */
#define BH (BB*HH)      /* 32   */
#define EPSF 1e-6f

// ---------------- device scratch (no allocation allowed) -------------------
__device__ float g_Q [BH*NN*DH];     // [bh][n][d]  raw Q projection (normalized in attn)
__device__ float g_Kt[BH*DH*NN];     // [bh][d][n]  K transposed (normalized by norm_k_cols)
__device__ float g_V [BH*NN*DH];     // [bh][n][d]  (tf32-rounded)
__device__ float g_O [BH*NN*DH];     // [bh][n][d]  attention out (tf32-rounded)
__device__ float g_Wt[4*DM*DM];      // W^T for Wq,Wk,Wv,Wo (tf32-rounded, contiguous)
__device__ float g_Xr[MM*DM];        // X rounded to tf32

// ---------------- helpers ---------------------------------------------------
__device__ __forceinline__ float tf32r(float x) {
    float y; asm("cvt.rna.tf32.f32 %0, %1;" : "=f"(y) : "f"(x)); return y;
}
__device__ __forceinline__ void cp16(uint32_t dst, const void* src) {
    asm volatile("cp.async.cg.shared.global [%0], [%1], 16;" :: "r"(dst), "l"(src));
}
__device__ __forceinline__ void cp_commit() { asm volatile("cp.async.commit_group;"); }
template<int N> __device__ __forceinline__ void cp_wait() {
    asm volatile("cp.async.wait_group %0;" :: "n"(N));
}
__device__ __forceinline__ uint32_t smem_u32(const void* p) {
    uint32_t a;
    asm("{ .reg .u64 t; cvta.to.shared.u64 t, %1; cvt.u32.u64 %0, t; }" : "=r"(a) : "l"(p));
    return a;
}
__device__ __forceinline__ void mma_tf32(float* c, const uint32_t* a, const uint32_t* b) {
    asm volatile(
        "mma.sync.aligned.m16n8k8.row.col.f32.tf32.tf32.f32 "
        "{%0,%1,%2,%3}, {%4,%5,%6,%7}, {%8,%9}, {%0,%1,%2,%3};"
        : "+f"(c[0]), "+f"(c[1]), "+f"(c[2]), "+f"(c[3])
        : "r"(a[0]), "r"(a[1]), "r"(a[2]), "r"(a[3]), "r"(b[0]), "r"(b[1]));
}

// ---------------------------------------------------------------------------
// Pre-passes: round X to tf32; transpose + round all 4 weights (one launch)
// ---------------------------------------------------------------------------
__global__ __launch_bounds__(256) void round_x(const float* __restrict__ X)
{
    int i = blockIdx.x * 256 + threadIdx.x;
    float4 v = ((const float4*)X)[i];
    v.x = tf32r(v.x); v.y = tf32r(v.y); v.z = tf32r(v.z); v.w = tf32r(v.w);
    ((float4*)g_Xr)[i] = v;
}

__global__ __launch_bounds__(256) void transpose_w4(
    const float* __restrict__ W0, const float* __restrict__ W1,
    const float* __restrict__ W2, const float* __restrict__ W3)
{
    __shared__ float ts[32][33];
    const int slot = blockIdx.z;
    const float* W = (slot == 0) ? W0 : (slot == 1) ? W1 : (slot == 2) ? W2 : W3;
    float* Wt = g_Wt + (size_t)slot * DM * DM;
    int bx = blockIdx.x * 32, by = blockIdx.y * 32;
    #pragma unroll
    for (int i = 0; i < 32; i += 8)
        ts[threadIdx.y + i][threadIdx.x] = W[(size_t)(by + threadIdx.y + i) * DM + bx + threadIdx.x];
    __syncthreads();
    #pragma unroll
    for (int i = 0; i < 32; i += 8)
        Wt[(size_t)(bx + threadIdx.y + i) * DM + by + threadIdx.x] = tf32r(ts[threadIdx.x][threadIdx.y + i]);
}

// ---------------------------------------------------------------------------
// mma.sync tf32 GEMM. BM=128 BN=128 BK=32, 256 threads, warp tile 64x32.
// mode -1: fused QKV projection, C[4096 x 3072]; proj = blockIdx.x>>3
//          (0 -> g_Q raw heads, 1 -> g_Kt raw transposed, 2 -> g_V tf32r heads)
// mode  3: out = g_O @ Wo^T + bo (A gathered from g_O heads layout)
// ---------------------------------------------------------------------------
#define BK 32
#define LDS_ROW 36
#define TILE_F (128*LDS_ROW)
#define GEMM_SMEM (4*TILE_F*4)
#define KTILES (DM/BK)

__global__ __launch_bounds__(256, 2) void gemm_tc(
    const float* __restrict__ A, const float* __restrict__ Bt,
    const float* __restrict__ bias, float* __restrict__ out, int mode)
{
    extern __shared__ float sm[];
    float* sA[2] = { sm,            sm + 2*TILE_F };
    float* sB[2] = { sm + TILE_F,   sm + 3*TILE_F };

    const int tid  = threadIdx.x;
    const int wid  = tid >> 5;
    const int lane = tid & 31;
    const int lr   = lane >> 2;
    const int lc   = lane & 3;
    const int wm   = (wid & 1) * 64;
    const int wn   = (wid >> 1) * 32;
    const int m0   = blockIdx.y * 128;

    const int bx    = blockIdx.x;
    const int emode = (mode < 0) ? (bx >> 3) : mode;         // epilogue mode
    const int c0g   = bx * 128;                              // B row offset (global)
    const int c0    = (mode < 0) ? ((bx & 7) * 128) : c0g;   // col within projection

    const int lrow = tid >> 1, lhalf = tid & 1;
    const int am = m0 + lrow;
    const int ab = am >> 11, an = am & (NN - 1);
    const float* brow_base = Bt + (size_t)(c0g + lrow) * DM;
    const uint32_t sa_u[2] = { smem_u32(sA[0]), smem_u32(sA[1]) };
    const uint32_t sb_u[2] = { smem_u32(sB[0]), smem_u32(sB[1]) };
    const uint32_t dst_off = (uint32_t)lrow * (LDS_ROW*4) + (uint32_t)lhalf * 64;

    auto load_tile = [&](int t, int buf) {
        const int k0 = t * BK + lhalf * 16;
        const float* arow;
        if (mode == 3) {
            arow = g_O + ((size_t)(ab * HH + (k0 >> 6)) * NN + an) * DH + (k0 & 63);
        } else {
            arow = A + (size_t)am * DM + k0;
        }
        const float* brow = brow_base + k0;
        #pragma unroll
        for (int f = 0; f < 4; f++) {
            cp16(sa_u[buf] + dst_off + f * 16, arow + f * 4);
            cp16(sb_u[buf] + dst_off + f * 16, brow + f * 4);
        }
    };

    float acc[4][4][4] = {};

    load_tile(0, 0);
    cp_commit();

    for (int t = 0; t < KTILES; t++) {
        const int p = t & 1;
        if (t + 1 < KTILES) {
            load_tile(t + 1, 1 - p);
            cp_commit();
            cp_wait<1>();
        } else {
            cp_wait<0>();
        }
        __syncthreads();

        const float* Ab = sA[p];
        const float* Bb = sB[p];
        #pragma unroll
        for (int kk = 0; kk < 4; kk++) {
            const int k0 = kk * 8;
            uint32_t af[4][4], bf[4][2];
            #pragma unroll
            for (int mt = 0; mt < 4; mt++) {
                const int rb = wm + mt * 16;
                af[mt][0] = __float_as_uint(Ab[(rb +     lr) * LDS_ROW + k0 +     lc]);
                af[mt][1] = __float_as_uint(Ab[(rb + 8 + lr) * LDS_ROW + k0 +     lc]);
                af[mt][2] = __float_as_uint(Ab[(rb +     lr) * LDS_ROW + k0 + 4 + lc]);
                af[mt][3] = __float_as_uint(Ab[(rb + 8 + lr) * LDS_ROW + k0 + 4 + lc]);
            }
            #pragma unroll
            for (int nt = 0; nt < 4; nt++) {
                const int cb = wn + nt * 8;
                bf[nt][0] = __float_as_uint(Bb[(cb + lr) * LDS_ROW + k0 +     lc]);
                bf[nt][1] = __float_as_uint(Bb[(cb + lr) * LDS_ROW + k0 + 4 + lc]);
            }
            #pragma unroll
            for (int mt = 0; mt < 4; mt++)
                #pragma unroll
                for (int nt = 0; nt < 4; nt++)
                    mma_tf32(acc[mt][nt], af[mt], bf[nt]);
        }
        __syncthreads();
    }

    #pragma unroll
    for (int mt = 0; mt < 4; mt++) {
        #pragma unroll
        for (int half = 0; half < 2; half++) {
            const int m = m0 + wm + mt * 16 + half * 8 + lr;
            const int b = m >> 11, n = m & (NN - 1);
            #pragma unroll
            for (int nt = 0; nt < 4; nt++) {
                const int c = c0 + wn + nt * 8 + 2 * lc;
                const float v0 = acc[mt][nt][half * 2 + 0];
                const float v1 = acc[mt][nt][half * 2 + 1];
                if (emode == 3) {
                    float2 bv = *(const float2*)&bias[c];
                    *(float2*)&out[(size_t)m * DM + c] = make_float2(v0 + bv.x, v1 + bv.y);
                } else if (emode == 1) {
                    const int h = c >> 6, d = c & 63;
                    float* dst = g_Kt + ((size_t)(b * HH + h)) * DH * NN + n;
                    dst[(size_t)d * NN]       = v0;
                    dst[(size_t)(d + 1) * NN] = v1;
                } else if (emode == 2) {
                    const int h = c >> 6, d = c & 63;
                    *(float2*)&g_V[(((size_t)(b * HH + h)) * NN + n) * DH + d] =
                        make_float2(tf32r(v0), tf32r(v1));
                } else {
                    const int h = c >> 6, d = c & 63;
                    *(float2*)&g_Q[(((size_t)(b * HH + h)) * NN + n) * DH + d] = make_float2(v0, v1);
                }
            }
        }
    }
}

// ---------------------------------------------------------------------------
// L2-normalize K columns (rounds to tf32)
// ---------------------------------------------------------------------------
__global__ __launch_bounds__(256) void norm_k_cols()
{
    int gc = blockIdx.x * 256 + threadIdx.x;
    int bh = gc >> 11, n = gc & (NN-1);
    float* p = g_Kt + (size_t)bh * DH * NN + n;
    float v[DH];
    float ss = 0.f;
    #pragma unroll
    for (int d = 0; d < DH; d++) { v[d] = p[(size_t)d*NN]; ss += v[d]*v[d]; }
    float sc = 1.0f / (sqrtf(ss) + EPSF);
    #pragma unroll
    for (int d = 0; d < DH; d++) p[(size_t)d*NN] = tf32r(v[d]*sc);
}

// ---------------------------------------------------------------------------
// Tensor-core flash attention, 2 CTAs/SM.
// Q normalization folded into staging: raw g_Q rows are L2-normalized
// (pair shuffle for sum-of-squares), scaled by 1/8, tf32-rounded into Qs.
// ---------------------------------------------------------------------------
#define KROW 72
#define QROW 68
#define KV_F (64*KROW)
#define AT_SMEM ((4*KV_F + 128*QROW)*4)      /* 108544 bytes */

__global__ __launch_bounds__(256, 2) void attn_tc()
{
    extern __shared__ float sm[];
    float* Ks[2] = { sm,          sm + 2*KV_F };
    float* Vs[2] = { sm + KV_F,   sm + 3*KV_F };
    float* Qs    = sm + 4*KV_F;

    const int tid  = threadIdx.x;
    const int wid  = tid >> 5;
    const int lane = tid & 31;
    const int lr   = lane >> 2;              // 0..7
    const int lc   = lane & 3;               // 0..3
    const int qt   = gridDim.x - 1 - blockIdx.x;   // heavy blocks first
    const int bh   = blockIdx.y;
    const int qbase = qt * 128;
    const int T    = 2 * qt + 2;             // 64-key tiles

    const float* Qp = g_Q  + (size_t)bh * NN * DH;
    const float* Kp = g_Kt + (size_t)bh * DH * NN;
    const float* Vp = g_V  + (size_t)bh * NN * DH;

    const uint32_t ks_u[2] = { smem_u32(Ks[0]), smem_u32(Ks[1]) };
    const uint32_t vs_u[2] = { smem_u32(Vs[0]), smem_u32(Vs[1]) };
    const int ldrow = tid >> 2, ldseg = tid & 3;

    auto load_kv = [&](int t, int buf) {
        const int kbase = t * 64;
        const float* ksrc = Kp + (size_t)ldrow * NN + kbase + ldseg * 16;
        const float* vsrc = Vp + (size_t)(kbase + ldrow) * DH + ldseg * 16;
        const uint32_t doff = (uint32_t)ldrow * (KROW*4) + (uint32_t)ldseg * 64;
        #pragma unroll
        for (int f = 0; f < 4; f++) {
            cp16(ks_u[buf] + doff + f * 16, ksrc + f * 4);
            cp16(vs_u[buf] + doff + f * 16, vsrc + f * 4);
        }
    };

    load_kv(0, 0);
    cp_commit();

    // ---- stage Q: L2-normalize + scale 1/8 + tf32 round ----
    {
        const int row = tid >> 1, halfq = tid & 1;
        const float4* src = (const float4*)(Qp + (size_t)(qbase + row) * DH + halfq * 32);
        float4 v[8];
        float ss = 0.f;
        #pragma unroll
        for (int f = 0; f < 8; f++) {
            v[f] = src[f];
            ss += v[f].x*v[f].x + v[f].y*v[f].y + v[f].z*v[f].z + v[f].w*v[f].w;
        }
        ss += __shfl_xor_sync(0xffffffffu, ss, 1);   // pair tid^1 holds other half of row
        const float sc = 0.125f / (sqrtf(ss) + EPSF);
        float4* dst = (float4*)(Qs + row * QROW + halfq * 32);
        #pragma unroll
        for (int f = 0; f < 8; f++)
            dst[f] = make_float4(tf32r(v[f].x * sc), tf32r(v[f].y * sc),
                                 tf32r(v[f].z * sc), tf32r(v[f].w * sc));
    }

    float m0r = -INFINITY, m1r = -INFINITY, l0 = 0.f, l1 = 0.f;
    float o[8][4] = {};
    const int q0row = qbase + 16 * wid + lr;
    const int q1row = q0row + 8;
    const float* q0 = Qs + (16 * wid +     lr) * QROW;
    const float* q1 = Qs + (16 * wid + 8 + lr) * QROW;

    for (int t = 0; t < T; t++) {
        const int p = t & 1;
        __syncthreads();                       // buf 1-p reads done
        if (t + 1 < T) {
            load_kv(t + 1, 1 - p);
            cp_commit();
            cp_wait<1>();
        } else {
            cp_wait<0>();
        }
        __syncthreads();                       // tile t resident; Qs visible (t=0)

        // ---- S = Q K^T (scaled) ----
        float s[8][4] = {};
        const float* Kb = Ks[p];
        #pragma unroll
        for (int k8 = 0; k8 < 8; k8++) {
            uint32_t af[4];
            af[0] = __float_as_uint(q0[8*k8 +     lc]);
            af[1] = __float_as_uint(q1[8*k8 +     lc]);
            af[2] = __float_as_uint(q0[8*k8 + 4 + lc]);
            af[3] = __float_as_uint(q1[8*k8 + 4 + lc]);
            const float* kr0 = Kb + (8*k8 +     lc) * KROW;
            const float* kr1 = Kb + (8*k8 + 4 + lc) * KROW;
            #pragma unroll
            for (int hh = 0; hh < 2; hh++) {
                uint32_t bk[4][2];
                #pragma unroll
                for (int q = 0; q < 4; q++) {
                    const int nt = 4*hh + q;
                    bk[q][0] = __float_as_uint(kr0[8*nt + lr]);
                    bk[q][1] = __float_as_uint(kr1[8*nt + lr]);
                }
                #pragma unroll
                for (int q = 0; q < 4; q++)
                    mma_tf32(s[4*hh + q], af, bk[q]);
            }
        }

        // ---- online softmax on C-fragments ----
        const int kbase = t * 64;
        const bool diag = (t >= T - 2);
        float mx0 = -INFINITY, mx1 = -INFINITY;
        #pragma unroll
        for (int nt = 0; nt < 8; nt++) {
            #pragma unroll
            for (int c = 0; c < 2; c++) {
                if (diag) {
                    const int j = kbase + 8*nt + 2*lc + c;
                    if (j > q0row) s[nt][c]     = -INFINITY;
                    if (j > q1row) s[nt][2 + c] = -INFINITY;
                }
                mx0 = fmaxf(mx0, s[nt][c]);
                mx1 = fmaxf(mx1, s[nt][2 + c]);
            }
        }
        mx0 = fmaxf(mx0, __shfl_xor_sync(0xffffffffu, mx0, 1));
        mx0 = fmaxf(mx0, __shfl_xor_sync(0xffffffffu, mx0, 2));
        mx1 = fmaxf(mx1, __shfl_xor_sync(0xffffffffu, mx1, 1));
        mx1 = fmaxf(mx1, __shfl_xor_sync(0xffffffffu, mx1, 2));
        const float mn0 = fmaxf(m0r, mx0), mn1 = fmaxf(m1r, mx1);
        const float cr0 = __expf(m0r - mn0), cr1 = __expf(m1r - mn1);
        float sum0 = 0.f, sum1 = 0.f;
        #pragma unroll
        for (int nt = 0; nt < 8; nt++) {
            #pragma unroll
            for (int c = 0; c < 2; c++) {
                float p0 = tf32r(__expf(s[nt][c]     - mn0));
                float p1 = tf32r(__expf(s[nt][2 + c] - mn1));
                s[nt][c] = p0;  s[nt][2 + c] = p1;
                sum0 += p0; sum1 += p1;
            }
        }
        sum0 += __shfl_xor_sync(0xffffffffu, sum0, 1);
        sum0 += __shfl_xor_sync(0xffffffffu, sum0, 2);
        sum1 += __shfl_xor_sync(0xffffffffu, sum1, 1);
        sum1 += __shfl_xor_sync(0xffffffffu, sum1, 2);
        l0 = l0 * cr0 + sum0;  m0r = mn0;
        l1 = l1 * cr1 + sum1;  m1r = mn1;
        #pragma unroll
        for (int nt = 0; nt < 8; nt++) {
            o[nt][0] *= cr0; o[nt][1] *= cr0;
            o[nt][2] *= cr1; o[nt][3] *= cr1;
        }

        // ---- O += P V  (C-frag -> A-frag via quad shuffles) ----
        const float* Vb = Vs[p];
        const int qbase_lane = lane & ~3;
        const int src1 = qbase_lane | (lc >> 1);
        const int src2 = qbase_lane | (2 + (lc >> 1));
        const bool odd = (lc & 1);
        #pragma unroll
        for (int jt = 0; jt < 8; jt++) {
            uint32_t ap[4];
            {
                float a0 = __shfl_sync(0xffffffffu, s[jt][0], src1);
                float b0 = __shfl_sync(0xffffffffu, s[jt][1], src1);
                float a1 = __shfl_sync(0xffffffffu, s[jt][2], src1);
                float b1 = __shfl_sync(0xffffffffu, s[jt][3], src1);
                float a2 = __shfl_sync(0xffffffffu, s[jt][0], src2);
                float b2 = __shfl_sync(0xffffffffu, s[jt][1], src2);
                float a3 = __shfl_sync(0xffffffffu, s[jt][2], src2);
                float b3 = __shfl_sync(0xffffffffu, s[jt][3], src2);
                ap[0] = __float_as_uint(odd ? b0 : a0);
                ap[1] = __float_as_uint(odd ? b1 : a1);
                ap[2] = __float_as_uint(odd ? b2 : a2);
                ap[3] = __float_as_uint(odd ? b3 : a3);
            }
            const float* vr0 = Vb + (8*jt +     lc) * KROW;
            const float* vr1 = Vb + (8*jt + 4 + lc) * KROW;
            #pragma unroll
            for (int hh = 0; hh < 2; hh++) {
                uint32_t bv[4][2];
                #pragma unroll
                for (int q = 0; q < 4; q++) {
                    const int nt = 4*hh + q;
                    bv[q][0] = __float_as_uint(vr0[8*nt + lr]);
                    bv[q][1] = __float_as_uint(vr1[8*nt + lr]);
                }
                #pragma unroll
                for (int q = 0; q < 4; q++)
                    mma_tf32(o[4*hh + q], ap, bv[q]);
            }
        }
    }

    // ---- epilogue ----
    const float inv0 = 1.0f / l0, inv1 = 1.0f / l1;
    float* Op = g_O + (size_t)bh * NN * DH;
    float* o0 = Op + (size_t)q0row * DH + 2 * lc;
    float* o1 = Op + (size_t)q1row * DH + 2 * lc;
    #pragma unroll
    for (int nt = 0; nt < 8; nt++) {
        *(float2*)(o0 + 8*nt) = make_float2(tf32r(o[nt][0] * inv0), tf32r(o[nt][1] * inv0));
        *(float2*)(o1 + 8*nt) = make_float2(tf32r(o[nt][2] * inv1), tf32r(o[nt][3] * inv1));
    }
}

// ---------------------------------------------------------------------------
extern "C" void kernel_launch(void* const* d_in, const int* in_sizes, int n_in,
                              void* d_out, int out_size)
{
    const float* X  = (const float*)d_in[0];
    const float* Wq = (const float*)d_in[1];
    const float* Wk = (const float*)d_in[2];
    const float* Wv = (const float*)d_in[3];
    const float* Wo = (const float*)d_in[4];
    const float* bo = (const float*)d_in[5];
    float* out = (float*)d_out;

    cudaFuncSetAttribute(gemm_tc, cudaFuncAttributeMaxDynamicSharedMemorySize, GEMM_SMEM);
    cudaFuncSetAttribute(attn_tc, cudaFuncAttributeMaxDynamicSharedMemorySize, AT_SMEM);

    round_x<<<(MM*DM)/(4*256), 256>>>(X);
    transpose_w4<<<dim3(32, 32, 4), dim3(32, 8)>>>(Wq, Wk, Wv, Wo);

    // __device__ symbols must be resolved to device addresses host-side.
    float* wt = nullptr;
    cudaGetSymbolAddress((void**)&wt, g_Wt);
    float* xr = nullptr;
    cudaGetSymbolAddress((void**)&xr, g_Xr);

    // fused QKV projection: C[4096 x 3072], 768 CTAs
    gemm_tc<<<dim3(3*DM/128, MM/128), 256, GEMM_SMEM>>>(xr, wt, nullptr, nullptr, -1);

    norm_k_cols<<<(BH*NN)/256, 256>>>();

    attn_tc<<<dim3(NN/128, BH), 256, AT_SMEM>>>();

    gemm_tc<<<dim3(DM/128, MM/128), 256, GEMM_SMEM>>>(nullptr, wt + 3*(size_t)DM*DM, bo, out, 3);
}